// round 7
// baseline (speedup 1.0000x reference)
#include <cuda_runtime.h>
#include <math.h>

#define NTOK 32768
#define C 128

// ---------------- device scratch (no allocations allowed) ----------------
__device__ float g_z[NTOK * C];      // residual stream
__device__ float g_zn[NTOK * C];     // LN output
__device__ float g_xmid[NTOK * C];   // conv-x output (channel = h*16+dh)
__device__ float g_fxmid[NTOK * C];  // conv-fx output
__device__ float g_swt[NTOK * 256];  // slice weights [n][h][g]
__device__ float g_norm[256];        // [h][g]
__device__ float g_toknum[4096];     // [h][g][dh]
__device__ float g_ot[4096];         // [h][g][dh]

__device__ __forceinline__ float gelu_exact(float v) {
    return 0.5f * v * (1.0f + erff(v * 0.70710678118654752f));
}

__device__ __forceinline__ float warp_sum(float s) {
#pragma unroll
    for (int o = 16; o; o >>= 1) s += __shfl_xor_sync(0xffffffffu, s, o);
    return s;
}
__device__ __forceinline__ float warp_max(float s) {
#pragma unroll
    for (int o = 16; o; o >>= 1) s = fmaxf(s, __shfl_xor_sync(0xffffffffu, s, o));
    return s;
}

// packed f32x2 helpers (Blackwell FFMA2 path — ptxas never auto-fuses this)
__device__ __forceinline__ unsigned long long pack2(float lo, float hi) {
    unsigned long long r;
    asm("mov.b64 %0, {%1, %2};" : "=l"(r) : "f"(lo), "f"(hi));
    return r;
}
__device__ __forceinline__ void ffma2(unsigned long long& d,
                                      unsigned long long a,
                                      unsigned long long b) {
    asm("fma.rn.f32x2 %0, %1, %2, %0;" : "+l"(d) : "l"(a), "l"(b));
}
__device__ __forceinline__ void unpack2(unsigned long long v, float& lo, float& hi) {
    asm("mov.b64 {%0, %1}, %2;" : "=f"(lo), "=f"(hi) : "l"(v));
}

// ---------------- pre-MLP: z = gelu(h@W1+b1)@W2+b2+placeholder ----------------
// 32 tokens per block, 128 threads.
__global__ void __launch_bounds__(128) k_pre(
    const float* __restrict__ x, const float* __restrict__ fx,
    const float* __restrict__ W1, const float* __restrict__ b1,
    const float* __restrict__ W2, const float* __restrict__ b2,
    const float* __restrict__ ph)
{
    __shared__ float h_s[32 * 4];
    __shared__ float mid_s[32 * 256];
    int tid = threadIdx.x;
    int tok0 = blockIdx.x * 32;

    for (int i = tid; i < 128; i += 128) {
        int t = i >> 2, j = i & 3;
        h_s[i] = (j < 3) ? x[(tok0 + t) * 3 + j] : fx[tok0 + t];
    }
    __syncthreads();

#pragma unroll
    for (int rep = 0; rep < 2; rep++) {
        int m = tid + rep * 128;
        float w0 = W1[0 * 256 + m], w1 = W1[1 * 256 + m];
        float w2 = W1[2 * 256 + m], w3 = W1[3 * 256 + m];
        float bb = b1[m];
#pragma unroll
        for (int t = 0; t < 32; t++) {
            float4 hv = ((const float4*)h_s)[t];
            float v = bb + hv.x * w0 + hv.y * w1 + hv.z * w2 + hv.w * w3;
            mid_s[t * 256 + m] = gelu_exact(v);
        }
    }
    __syncthreads();

    int o = tid;
    float acc[32];
#pragma unroll
    for (int t = 0; t < 32; t++) acc[t] = 0.0f;
    for (int m4 = 0; m4 < 64; m4++) {
        int m = m4 * 4;
        float w0 = W2[(m + 0) * 128 + o], w1 = W2[(m + 1) * 128 + o];
        float w2 = W2[(m + 2) * 128 + o], w3 = W2[(m + 3) * 128 + o];
#pragma unroll
        for (int t = 0; t < 32; t++) {
            float4 v = ((const float4*)mid_s)[t * 64 + m4];
            acc[t] += v.x * w0 + v.y * w1 + v.z * w2 + v.w * w3;
        }
    }
    float bb = b2[o] + ph[o];
#pragma unroll
    for (int t = 0; t < 32; t++) g_z[(tok0 + t) * 128 + o] = acc[t] + bb;
}

// ---------------- LayerNorm: zn = LN(z)*g+b. warp per token ----------------
__global__ void __launch_bounds__(256) k_ln(
    const float* __restrict__ g, const float* __restrict__ b)
{
    int warp = threadIdx.x >> 5, lane = threadIdx.x & 31;
    int n = blockIdx.x * 8 + warp;
    float4 v = ((const float4*)g_z)[n * 32 + lane];
    float s = warp_sum(v.x + v.y + v.z + v.w);
    float mu = s * (1.0f / 128.0f);
    float q = warp_sum(v.x * v.x + v.y * v.y + v.z * v.z + v.w * v.w);
    float var = q * (1.0f / 128.0f) - mu * mu;
    float inv = rsqrtf(var + 1e-5f);
    float4 gg = ((const float4*)g)[lane];
    float4 bb = ((const float4*)b)[lane];
    float4 y;
    y.x = (v.x - mu) * inv * gg.x + bb.x;
    y.y = (v.y - mu) * inv * gg.y + bb.y;
    y.z = (v.z - mu) * inv * gg.z + bb.z;
    y.w = (v.w - mu) * inv * gg.w + bb.w;
    ((float4*)g_zn)[n * 32 + lane] = y;
}

// ---------------- conv3d 3x3x3, SAME, C=128->128 (both convs) ----------------
// grid (8,8,8): x=i-tile, y=j-tile, z in [0,8): z<4 -> convx, else convfx; oc=(z&3)*32.
// Block: 256 threads. Tile: 4x4 (i,j) x 32 k x 32 output channels.
// Thread: 4 o-PAIRS x 8 k via packed fma.rn.f32x2 (FFMA2): weights paired along
// output channel (transposed+swizzled smem layout -> aligned LDS.64 broadcast),
// inputs broadcast-packed {x,x} once per (c,ab) and reused across 96 FFMA2.
__global__ void __launch_bounds__(256) k_conv(
    const float* __restrict__ wx, const float* __restrict__ bx,
    const float* __restrict__ wf, const float* __restrict__ bf)
{
    const bool isfx = blockIdx.z >= 4;
    const float* __restrict__ wbase = isfx ? wf : wx;
    const float* __restrict__ bias = isfx ? bf : bx;
    float* __restrict__ out = isfx ? g_fxmid : g_xmid;
    int oc = (blockIdx.z & 3) * 32;
    int i0 = blockIdx.x * 4, j0 = blockIdx.y * 4;

    __shared__ float xs[4 * 36 * 35];                 // [c][line(6x6)][k(-1..32) pitch 35]
    __shared__ __align__(16) float ws[4 * 27 * 32];   // [c][tap][o rotated by 2*(row&15)]

    int tid = threadIdx.x;
    int ogrp = tid >> 6;            // 0..3 (4 o-pairs each)
    int tg = tid & 63;
    int line = tg >> 2;             // 0..15
    int kb = (tg & 3) * 8;          // 0,8,16,24
    int li = line >> 2, lj = line & 3;

    unsigned long long acc2[4][8];  // [o-pair][kk], halves = (o_lo, o_hi)
#pragma unroll
    for (int op = 0; op < 4; op++)
#pragma unroll
        for (int k = 0; k < 8; k++) acc2[op][k] = 0ull;

    for (int cb = 0; cb < 128; cb += 4) {
        __syncthreads();
        // load input tile: 36 lines x 34 k x 4 channels
        for (int idx = tid; idx < 1224; idx += 256) {
            int ln = idx / 34;
            int ks = idx - ln * 34;
            int ii = ln / 6, jj = ln - ii * 6;
            int gi = i0 + ii - 1, gj = j0 + jj - 1, gk = ks - 1;
            float4 v = make_float4(0.f, 0.f, 0.f, 0.f);
            if ((unsigned)gi < 32u && (unsigned)gj < 32u && (unsigned)gk < 32u) {
                v = *((const float4*)&g_zn[(((gi << 10) + (gj << 5) + gk) << 7) + cb]);
            }
            int base = ln * 35 + ks;
            xs[base + 0 * 1260] = v.x;
            xs[base + 1 * 1260] = v.y;
            xs[base + 2 * 1260] = v.z;
            xs[base + 3 * 1260] = v.w;
        }
        // load weights (coalesced gmem read) -> transposed smem [c][tap][o],
        // with even bank rotation so the transpose store is ~2-way instead of 27-way
        // conflicted, while o-pairs stay 8B-aligned.
        for (int idx = tid; idx < 3456; idx += 256) {
            int o = idx / 108;
            int r = idx - o * 108;
            int c = r / 27;
            int tp = r - c * 27;
            int row = c * 27 + tp;
            int rot = (row & 15) * 2;
            ws[row * 32 + ((o + rot) & 31)] =
                wbase[((oc + o) * 128 + (cb + c)) * 27 + tp];
        }
        __syncthreads();

#pragma unroll 1
        for (int c = 0; c < 4; c++) {
#pragma unroll 1
            for (int ab = 0; ab < 9; ab++) {
                int a = ab / 3, b = ab - a * 3;
                const float* xr = &xs[c * 1260 + ((li + a) * 6 + (lj + b)) * 35 + kb];
                unsigned long long xb2[10];
#pragma unroll
                for (int j = 0; j < 10; j++) {
                    float xv = xr[j];
                    xb2[j] = pack2(xv, xv);
                }
#pragma unroll
                for (int cc = 0; cc < 3; cc++) {
                    int row = c * 27 + ab * 3 + cc;
                    int rot = (row & 15) * 2;
                    const unsigned long long* wrow =
                        (const unsigned long long*)&ws[row * 32];
#pragma unroll
                    for (int op = 0; op < 4; op++) {
                        unsigned long long w2 =
                            wrow[((ogrp * 8 + op * 2 + rot) & 31) >> 1];
#pragma unroll
                        for (int kk = 0; kk < 8; kk++)
                            ffma2(acc2[op][kk], w2, xb2[kk + cc]);
                    }
                }
            }
        }
    }

    int gi = i0 + li, gj = j0 + lj;
    int nbase = (gi << 10) + (gj << 5) + kb;
#pragma unroll
    for (int op = 0; op < 4; op++) {
        int och_lo = oc + ogrp * 8 + op * 2;
        float blo = bias[och_lo], bhi = bias[och_lo + 1];
#pragma unroll
        for (int kk = 0; kk < 8; kk++) {
            float lo, hi;
            unpack2(acc2[op][kk], lo, hi);
            out[(nbase + kk) * 128 + och_lo] = lo + blo;
            out[(nbase + kk) * 128 + och_lo + 1] = hi + bhi;
        }
    }
}

// ---------------- zero slice accumulators ----------------
__global__ void k_zero() {
    int t = threadIdx.x;
    g_norm[t] = 0.0f;
    for (int i = t; i < 4096; i += 256) g_toknum[i] = 0.0f;
}

// ---------------- slice softmax + N-reductions ----------------
// 128 blocks x 256 threads; thread = (h=tid/32, g=lane); 256 tokens per block.
__global__ void __launch_bounds__(256) k_slice(
    const float* __restrict__ sw, const float* __restrict__ sb,
    const float* __restrict__ temp)
{
    __shared__ float sw_s[512];
    __shared__ float sb_s[32];
    __shared__ float xm_s[8 * 128];
    __shared__ float fx_s[8 * 128];
    int tid = threadIdx.x;
    int h = tid >> 5;
    int g = tid & 31;
    for (int i = tid; i < 512; i += 256) sw_s[i] = sw[i];
    if (tid < 32) sb_s[tid] = sb[tid];
    float invt = 1.0f / temp[h];
    float nacc = 0.0f;
    float tacc[16];
#pragma unroll
    for (int d = 0; d < 16; d++) tacc[d] = 0.0f;
    int tok0 = blockIdx.x * 256;

    for (int bt = 0; bt < 32; bt++) {
        __syncthreads();
        int tb = tok0 + bt * 8;
        for (int i = tid; i < 1024; i += 256) {
            int t = i >> 7, c = i & 127;
            xm_s[i] = g_xmid[(tb + t) * 128 + c];
            fx_s[i] = g_fxmid[(tb + t) * 128 + c];
        }
        __syncthreads();
#pragma unroll 1
        for (int t = 0; t < 8; t++) {
            float lg = sb_s[g];
#pragma unroll
            for (int d = 0; d < 16; d++) lg += xm_s[t * 128 + h * 16 + d] * sw_s[d * 32 + g];
            lg *= invt;
            float m = warp_max(lg);
            float e = expf(lg - m);
            float s = warp_sum(e);
            float w = e / s;
            g_swt[(tb + t) * 256 + tid] = w;
            nacc += w;
#pragma unroll
            for (int d = 0; d < 16; d++) tacc[d] += fx_s[t * 128 + h * 16 + d] * w;
        }
    }
    atomicAdd(&g_norm[tid], nacc);
#pragma unroll
    for (int d = 0; d < 16; d++) atomicAdd(&g_toknum[tid * 16 + d], tacc[d]);
}

// ---------------- tiny slice attention (1 block, 256 threads) ----------------
__global__ void __launch_bounds__(256) k_attn(
    const float* __restrict__ wq, const float* __restrict__ wk,
    const float* __restrict__ wv)
{
    __shared__ float k_s[4096];
    __shared__ float v_s[4096];
    int tid = threadIdx.x;
    int h = tid >> 5;
    float tokr[16];
    float nrm = g_norm[tid] + 1e-5f;
#pragma unroll
    for (int d = 0; d < 16; d++) tokr[d] = g_toknum[tid * 16 + d] / nrm;
    float q[16];
#pragma unroll
    for (int dd = 0; dd < 16; dd++) {
        float aq = 0.f, ak = 0.f, av = 0.f;
#pragma unroll
        for (int d = 0; d < 16; d++) {
            aq += tokr[d] * wq[d * 16 + dd];
            ak += tokr[d] * wk[d * 16 + dd];
            av += tokr[d] * wv[d * 16 + dd];
        }
        q[dd] = aq;
        k_s[tid * 16 + dd] = ak;
        v_s[tid * 16 + dd] = av;
    }
    __syncthreads();
    float p[32];
    float mx = -1e30f;
#pragma unroll 1
    for (int g2 = 0; g2 < 32; g2++) {
        float s = 0.f;
#pragma unroll
        for (int d = 0; d < 16; d++) s += q[d] * k_s[(h * 32 + g2) * 16 + d];
        s *= 0.25f;
        p[g2] = s;
        mx = fmaxf(mx, s);
    }
    float sum = 0.f;
#pragma unroll
    for (int g2 = 0; g2 < 32; g2++) { p[g2] = expf(p[g2] - mx); sum += p[g2]; }
    float inv = 1.0f / sum;
#pragma unroll 1
    for (int c = 0; c < 16; c++) {
        float o = 0.f;
#pragma unroll
        for (int g2 = 0; g2 < 32; g2++) o += p[g2] * v_s[(h * 32 + g2) * 16 + c];
        g_ot[tid * 16 + c] = o * inv;
    }
}

// ---------------- de-slice + wo projection + residual ----------------
// 16 tokens per block, 128 threads.
__global__ void __launch_bounds__(128) k_deslice(
    const float* __restrict__ wo, const float* __restrict__ bo)
{
    __shared__ float swt_s[16 * 256];
    __shared__ float tmp_s[16 * 128];
    int tid = threadIdx.x;
    int tok0 = blockIdx.x * 16;
    for (int i = tid; i < 4096; i += 128) swt_s[i] = g_swt[tok0 * 256 + i];
    __syncthreads();
    {
        int c = tid, h = c >> 4, cc = c & 15;
        float acc[16];
#pragma unroll
        for (int t = 0; t < 16; t++) acc[t] = 0.0f;
        for (int g = 0; g < 32; g++) {
            float ov = g_ot[(h * 32 + g) * 16 + cc];
#pragma unroll
            for (int t = 0; t < 16; t++) acc[t] += swt_s[t * 256 + h * 32 + g] * ov;
        }
#pragma unroll
        for (int t = 0; t < 16; t++) tmp_s[t * 128 + c] = acc[t];
    }
    __syncthreads();
    {
        int o = tid;
        float facc[16];
#pragma unroll
        for (int t = 0; t < 16; t++) facc[t] = 0.0f;
        for (int m4 = 0; m4 < 32; m4++) {
            int m = m4 * 4;
            float w0 = wo[(m + 0) * 128 + o], w1 = wo[(m + 1) * 128 + o];
            float w2 = wo[(m + 2) * 128 + o], w3 = wo[(m + 3) * 128 + o];
#pragma unroll
            for (int t = 0; t < 16; t++) {
                float4 v = ((const float4*)tmp_s)[t * 32 + m4];
                facc[t] += v.x * w0 + v.y * w1 + v.z * w2 + v.w * w3;
            }
        }
        float bv = bo[o];
#pragma unroll
        for (int t = 0; t < 16; t++) g_z[(tok0 + t) * 128 + o] += facc[t] + bv;
    }
}

// ---------------- MLP: z += gelu(zn@W1+b1)@W2+b2. 32 tokens/block ----------------
__global__ void __launch_bounds__(128) k_mlp(
    const float* __restrict__ W1, const float* __restrict__ b1,
    const float* __restrict__ W2, const float* __restrict__ b2)
{
    __shared__ float zn_s[32 * 128];
    __shared__ float mid_s[32 * 128];
    int tid = threadIdx.x;
    int tok0 = blockIdx.x * 32;
    for (int i = tid; i < 4096; i += 128) zn_s[i] = g_zn[tok0 * 128 + i];
    __syncthreads();
    {
        float acc[32];
#pragma unroll
        for (int t = 0; t < 32; t++) acc[t] = 0.0f;
        for (int c4 = 0; c4 < 32; c4++) {
            int c = c4 * 4;
            float w0 = W1[(c + 0) * 128 + tid], w1 = W1[(c + 1) * 128 + tid];
            float w2 = W1[(c + 2) * 128 + tid], w3 = W1[(c + 3) * 128 + tid];
#pragma unroll
            for (int t = 0; t < 32; t++) {
                float4 v = ((const float4*)zn_s)[t * 32 + c4];
                acc[t] += v.x * w0 + v.y * w1 + v.z * w2 + v.w * w3;
            }
        }
        float bb = b1[tid];
#pragma unroll
        for (int t = 0; t < 32; t++) mid_s[t * 128 + tid] = gelu_exact(acc[t] + bb);
    }
    __syncthreads();
    {
        float acc[32];
#pragma unroll
        for (int t = 0; t < 32; t++) acc[t] = 0.0f;
        for (int m4 = 0; m4 < 32; m4++) {
            int m = m4 * 4;
            float w0 = W2[(m + 0) * 128 + tid], w1 = W2[(m + 1) * 128 + tid];
            float w2 = W2[(m + 2) * 128 + tid], w3 = W2[(m + 3) * 128 + tid];
#pragma unroll
            for (int t = 0; t < 32; t++) {
                float4 v = ((const float4*)mid_s)[t * 32 + m4];
                acc[t] += v.x * w0 + v.y * w1 + v.z * w2 + v.w * w3;
            }
        }
        float bb = b2[tid];
#pragma unroll
        for (int t = 0; t < 32; t++) g_z[(tok0 + t) * 128 + tid] += acc[t] + bb;
    }
}

// ---------------- final LN + head ----------------
__global__ void __launch_bounds__(256) k_final(
    const float* __restrict__ g, const float* __restrict__ b,
    const float* __restrict__ ow, const float* __restrict__ ob,
    float* __restrict__ out)
{
    int warp = threadIdx.x >> 5, lane = threadIdx.x & 31;
    int n = blockIdx.x * 8 + warp;
    float4 v = ((const float4*)g_z)[n * 32 + lane];
    float s = warp_sum(v.x + v.y + v.z + v.w);
    float mu = s * (1.0f / 128.0f);
    float q = warp_sum(v.x * v.x + v.y * v.y + v.z * v.z + v.w * v.w);
    float var = q * (1.0f / 128.0f) - mu * mu;
    float inv = rsqrtf(var + 1e-5f);
    float4 gg = ((const float4*)g)[lane];
    float4 bb = ((const float4*)b)[lane];
    float4 w4 = ((const float4*)ow)[lane];
    float y0 = (v.x - mu) * inv * gg.x + bb.x;
    float y1 = (v.y - mu) * inv * gg.y + bb.y;
    float y2 = (v.z - mu) * inv * gg.z + bb.z;
    float y3 = (v.w - mu) * inv * gg.w + bb.w;
    float p = warp_sum(y0 * w4.x + y1 * w4.y + y2 * w4.z + y3 * w4.w);
    if (lane == 0) out[n] = p + ob[0];
}

// ---------------- host launch ----------------
extern "C" void kernel_launch(void* const* d_in, const int* in_sizes, int n_in,
                              void* d_out, int out_size)
{
    const float* x        = (const float*)d_in[0];
    const float* fx       = (const float*)d_in[1];
    const float* pre_w1   = (const float*)d_in[2];
    const float* pre_b1   = (const float*)d_in[3];
    const float* pre_w2   = (const float*)d_in[4];
    const float* pre_b2   = (const float*)d_in[5];
    const float* place    = (const float*)d_in[6];
    const float* ln1_g    = (const float*)d_in[7];
    const float* ln1_b    = (const float*)d_in[8];
    const float* convx_w  = (const float*)d_in[9];
    const float* convx_b  = (const float*)d_in[10];
    const float* convfx_w = (const float*)d_in[11];
    const float* convfx_b = (const float*)d_in[12];
    const float* slice_w  = (const float*)d_in[13];
    const float* slice_b  = (const float*)d_in[14];
    const float* temp     = (const float*)d_in[15];
    const float* wq       = (const float*)d_in[16];
    const float* wk       = (const float*)d_in[17];
    const float* wv       = (const float*)d_in[18];
    const float* wo       = (const float*)d_in[19];
    const float* bo       = (const float*)d_in[20];
    const float* ln2_g    = (const float*)d_in[21];
    const float* ln2_b    = (const float*)d_in[22];
    const float* mlp_w1   = (const float*)d_in[23];
    const float* mlp_b1   = (const float*)d_in[24];
    const float* mlp_w2   = (const float*)d_in[25];
    const float* mlp_b2   = (const float*)d_in[26];
    const float* ln3_g    = (const float*)d_in[27];
    const float* ln3_b    = (const float*)d_in[28];
    const float* out_w    = (const float*)d_in[29];
    const float* out_b    = (const float*)d_in[30];
    float* out = (float*)d_out;

    const int WCONV = 128 * 128 * 27;

    k_pre<<<NTOK / 32, 128>>>(x, fx, pre_w1, pre_b1, pre_w2, pre_b2, place);

    for (int l = 0; l < 2; l++) {
        k_ln<<<NTOK / 8, 256>>>(ln1_g + l * 128, ln1_b + l * 128);
        k_conv<<<dim3(8, 8, 8), 256>>>(convx_w + l * WCONV, convx_b + l * 128,
                                       convfx_w + l * WCONV, convfx_b + l * 128);
        k_zero<<<1, 256>>>();
        k_slice<<<128, 256>>>(slice_w + l * 512, slice_b + l * 32, temp + l * 8);
        k_attn<<<1, 256>>>(wq + l * 256, wk + l * 256, wv + l * 256);
        k_deslice<<<NTOK / 16, 128>>>(wo + l * 16384, bo + l * 128);
        k_ln<<<NTOK / 8, 256>>>(ln2_g + l * 128, ln2_b + l * 128);
        k_mlp<<<NTOK / 32, 128>>>(mlp_w1 + l * 16384, mlp_b1 + l * 128,
                                  mlp_w2 + l * 16384, mlp_b2 + l * 128);
    }
    k_final<<<NTOK / 8, 256>>>(ln3_g, ln3_b, out_w, out_b, out);
}

// round 9
// speedup vs baseline: 2.8898x; 2.8898x over previous
#include <cuda_runtime.h>
#include <cuda_bf16.h>
#include <math.h>
#include <stdint.h>

#define NTOK 32768
#define C 128
#define XP 40   // bf16 pitch for ic dimension (conflict-free ldmatrix)

// ---------------- device scratch (no allocations allowed) ----------------
__device__ float g_z[NTOK * C];      // residual stream
__device__ float g_zn[NTOK * C];     // LN output (fp32)
__device__ float g_xmid[NTOK * C];   // conv-x output
__device__ float g_fxmid[NTOK * C];  // conv-fx output
__device__ float g_swt[NTOK * 256];  // slice weights [n][h][g]
__device__ float g_norm[256];        // [h][g]
__device__ float g_toknum[4096];     // [h][g][dh]
__device__ float g_ot[4096];         // [h][g][dh]
__device__ __nv_bfloat16 g_znh[NTOK * C];       // LN output hi (bf16)
__device__ __nv_bfloat16 g_znl[NTOK * C];       // LN output lo (bf16)
__device__ __nv_bfloat16 g_wh[4 * 27 * 128 * 128]; // conv weights hi [sel][tap][oc][ic]
__device__ __nv_bfloat16 g_wl[4 * 27 * 128 * 128]; // conv weights lo

__device__ __forceinline__ float gelu_exact(float v) {
    return 0.5f * v * (1.0f + erff(v * 0.70710678118654752f));
}

__device__ __forceinline__ float warp_sum(float s) {
#pragma unroll
    for (int o = 16; o; o >>= 1) s += __shfl_xor_sync(0xffffffffu, s, o);
    return s;
}
__device__ __forceinline__ float warp_max(float s) {
#pragma unroll
    for (int o = 16; o; o >>= 1) s = fmaxf(s, __shfl_xor_sync(0xffffffffu, s, o));
    return s;
}

__device__ __forceinline__ void ldsm4(uint32_t* r, uint32_t addr) {
    asm volatile("ldmatrix.sync.aligned.m8n8.x4.shared.b16 {%0,%1,%2,%3}, [%4];"
        : "=r"(r[0]), "=r"(r[1]), "=r"(r[2]), "=r"(r[3]) : "r"(addr));
}
__device__ __forceinline__ void mma_bf16(float* d, const uint32_t* a,
                                         uint32_t b0, uint32_t b1) {
    asm volatile(
        "mma.sync.aligned.m16n8k16.row.col.f32.bf16.bf16.f32 "
        "{%0,%1,%2,%3}, {%4,%5,%6,%7}, {%8,%9}, {%0,%1,%2,%3};"
        : "+f"(d[0]), "+f"(d[1]), "+f"(d[2]), "+f"(d[3])
        : "r"(a[0]), "r"(a[1]), "r"(a[2]), "r"(a[3]), "r"(b0), "r"(b1));
}

// ---------------- weight conversion: fp32 [oc][ic][tap] -> bf16 hi/lo [sel][tap][oc][ic]
__global__ void __launch_bounds__(256) k_cvt_w(
    const float* __restrict__ wx, const float* __restrict__ wf)
{
    int sel = blockIdx.y;                       // layer*2 + conv
    int lin = blockIdx.x * 256 + threadIdx.x;   // < 27*128*128 = 442368
    int tap = lin / 16384;
    int r = lin - tap * 16384;
    int oc = r >> 7, ic = r & 127;
    const float* src = ((sel & 1) ? wf : wx) + (sel >> 1) * (128 * 128 * 27);
    float v = src[(oc * 128 + ic) * 27 + tap];
    __nv_bfloat16 h = __float2bfloat16(v);
    float lo = v - __bfloat162float(h);
    int out = sel * 442368 + lin;
    g_wh[out] = h;
    g_wl[out] = __float2bfloat16(lo);
}

// ---------------- pre-MLP: z = gelu(h@W1+b1)@W2+b2+placeholder ----------------
__global__ void __launch_bounds__(128) k_pre(
    const float* __restrict__ x, const float* __restrict__ fx,
    const float* __restrict__ W1, const float* __restrict__ b1,
    const float* __restrict__ W2, const float* __restrict__ b2,
    const float* __restrict__ ph)
{
    __shared__ float h_s[32 * 4];
    __shared__ float mid_s[32 * 256];
    int tid = threadIdx.x;
    int tok0 = blockIdx.x * 32;

    for (int i = tid; i < 128; i += 128) {
        int t = i >> 2, j = i & 3;
        h_s[i] = (j < 3) ? x[(tok0 + t) * 3 + j] : fx[tok0 + t];
    }
    __syncthreads();

#pragma unroll
    for (int rep = 0; rep < 2; rep++) {
        int m = tid + rep * 128;
        float w0 = W1[0 * 256 + m], w1 = W1[1 * 256 + m];
        float w2 = W1[2 * 256 + m], w3 = W1[3 * 256 + m];
        float bb = b1[m];
#pragma unroll
        for (int t = 0; t < 32; t++) {
            float4 hv = ((const float4*)h_s)[t];
            float v = bb + hv.x * w0 + hv.y * w1 + hv.z * w2 + hv.w * w3;
            mid_s[t * 256 + m] = gelu_exact(v);
        }
    }
    __syncthreads();

    int o = tid;
    float acc[32];
#pragma unroll
    for (int t = 0; t < 32; t++) acc[t] = 0.0f;
    for (int m4 = 0; m4 < 64; m4++) {
        int m = m4 * 4;
        float w0 = W2[(m + 0) * 128 + o], w1 = W2[(m + 1) * 128 + o];
        float w2 = W2[(m + 2) * 128 + o], w3 = W2[(m + 3) * 128 + o];
#pragma unroll
        for (int t = 0; t < 32; t++) {
            float4 v = ((const float4*)mid_s)[t * 64 + m4];
            acc[t] += v.x * w0 + v.y * w1 + v.z * w2 + v.w * w3;
        }
    }
    float bb = b2[o] + ph[o];
#pragma unroll
    for (int t = 0; t < 32; t++) g_z[(tok0 + t) * 128 + o] = acc[t] + bb;
}

// ---------------- LayerNorm: zn = LN(z)*g+b (fp32 + bf16 hi/lo) ----------------
__global__ void __launch_bounds__(256) k_ln(
    const float* __restrict__ g, const float* __restrict__ b)
{
    int warp = threadIdx.x >> 5, lane = threadIdx.x & 31;
    int n = blockIdx.x * 8 + warp;
    float4 v = ((const float4*)g_z)[n * 32 + lane];
    float s = warp_sum(v.x + v.y + v.z + v.w);
    float mu = s * (1.0f / 128.0f);
    float q = warp_sum(v.x * v.x + v.y * v.y + v.z * v.z + v.w * v.w);
    float var = q * (1.0f / 128.0f) - mu * mu;
    float inv = rsqrtf(var + 1e-5f);
    float4 gg = ((const float4*)g)[lane];
    float4 bb = ((const float4*)b)[lane];
    float4 y;
    y.x = (v.x - mu) * inv * gg.x + bb.x;
    y.y = (v.y - mu) * inv * gg.y + bb.y;
    y.z = (v.z - mu) * inv * gg.z + bb.z;
    y.w = (v.w - mu) * inv * gg.w + bb.w;
    ((float4*)g_zn)[n * 32 + lane] = y;
    // bf16 hi/lo for the tensor-core conv
    __nv_bfloat162 h0, h1, l0, l1;
    h0.x = __float2bfloat16(y.x); l0.x = __float2bfloat16(y.x - __bfloat162float(h0.x));
    h0.y = __float2bfloat16(y.y); l0.y = __float2bfloat16(y.y - __bfloat162float(h0.y));
    h1.x = __float2bfloat16(y.z); l1.x = __float2bfloat16(y.z - __bfloat162float(h1.x));
    h1.y = __float2bfloat16(y.w); l1.y = __float2bfloat16(y.w - __bfloat162float(h1.y));
    ((__nv_bfloat162*)g_znh)[n * 64 + lane * 2 + 0] = h0;
    ((__nv_bfloat162*)g_znh)[n * 64 + lane * 2 + 1] = h1;
    ((__nv_bfloat162*)g_znl)[n * 64 + lane * 2 + 0] = l0;
    ((__nv_bfloat162*)g_znl)[n * 64 + lane * 2 + 1] = l1;
}

// ---------------- conv3d 3x3x3 via bf16 split-precision tensor cores ----------------
// grid (8 j-tiles, 32 i, 2 conv). Block 256 thr = 8 warps.
// Block tile: 128 tokens (fixed i, 4 j, 32 k) x 128 oc. K-loop: 4 ic-chunks x 27 taps.
// Warp: 16 token-rows x 128 oc, acc 16x(m16n8) fragments.
// 3 mma passes per step: Ah*Bh + Ah*Bl + Al*Bh  (drop lo*lo, err ~2^-16).
#define CONV_SMEM (2*612*XP*2 + 2*2*128*XP*2 + 512)
__global__ void __launch_bounds__(256) k_conv_mma(
    const float* __restrict__ bx, const float* __restrict__ bf, int layer)
{
    extern __shared__ char sm_raw[];
    __nv_bfloat16* xs_h = (__nv_bfloat16*)sm_raw;       // [612][XP]
    __nv_bfloat16* xs_l = xs_h + 612 * XP;
    __nv_bfloat16* wbuf = xs_l + 612 * XP;              // [2 buf][2 hl][128][XP]
    float* bias_s = (float*)(wbuf + 2 * 2 * 128 * XP);

    const int tid = threadIdx.x, lane = tid & 31, warp = tid >> 5;
    const int z = blockIdx.z;
    const int sel = layer * 2 + z;
    const float* bias = z ? bf : bx;
    float* out = z ? g_fxmid : g_xmid;
    const int jl = warp >> 1, k0 = (warp & 1) * 16;

    uint32_t su = (uint32_t)__cvta_generic_to_shared(sm_raw);
    const uint32_t xs_h_u = su;
    const uint32_t xs_l_u = su + 612 * XP * 2;
    const uint32_t wb_u   = su + 2 * 612 * XP * 2;

    if (tid < 128) bias_s[tid] = bias[tid];

    float acc[16][4];
#pragma unroll
    for (int n = 0; n < 16; n++) {
        acc[n][0] = acc[n][1] = acc[n][2] = acc[n][3] = 0.f;
    }

    uint4 wr[4];
    // prefetch weights for it=0 (tap 0, chunk 0)
    {
        const uint4* srcH = (const uint4*)(g_wh + (size_t)sel * 27 * 16384);
        const uint4* srcL = (const uint4*)(g_wl + (size_t)sel * 27 * 16384);
#pragma unroll
        for (int r = 0; r < 4; r++) {
            int idx = tid + 256 * r; int isl = idx >> 9; int lin = idx & 511;
            int oc = lin >> 2, q = lin & 3;
            const uint4* s = isl ? srcL : srcH;
            wr[r] = s[oc * 16 + q];
        }
    }

    for (int it = 0; it < 108; it++) {
        int cb = it / 27, t = it - cb * 27;
        if (t == 0) {
            __syncthreads();   // protect xs from previous chunk's readers
            // stage halo neighborhood (3x6x34 positions x 32 ic) hi+lo
            for (int idx = tid; idx < 4896; idx += 256) {
                int arr = idx >= 2448;
                int lin = arr ? idx - 2448 : idx;
                int pos = lin >> 2, q = lin & 3;
                int ii = pos / 204; int rem = pos - ii * 204;
                int jj = rem / 34;  int kk = rem - jj * 34;
                int gi = (int)blockIdx.y + ii - 1;
                int gj = (int)blockIdx.x * 4 + jj - 1;
                int gk = kk - 1;
                uint4 v = make_uint4(0u, 0u, 0u, 0u);
                if ((unsigned)gi < 32u && (unsigned)gj < 32u && (unsigned)gk < 32u) {
                    int tokn = (gi << 10) + (gj << 5) + gk;
                    const uint4* srcp = arr ? (const uint4*)g_znl : (const uint4*)g_znh;
                    v = srcp[tokn * 16 + cb * 4 + q];
                }
                char* dst = (char*)(arr ? xs_l : xs_h) + pos * (XP * 2) + q * 16;
                *(uint4*)dst = v;
            }
        }
        // weights regs -> smem buffer (it&1)
        {
            int buf = it & 1;
#pragma unroll
            for (int r = 0; r < 4; r++) {
                int idx = tid + 256 * r; int isl = idx >> 9; int lin = idx & 511;
                int oc = lin >> 2, q = lin & 3;
                char* dst = (char*)wbuf + ((buf * 2 + isl) * 128 * XP + oc * XP) * 2 + q * 16;
                *(uint4*)dst = wr[r];
            }
        }
        __syncthreads();
        // prefetch next iteration's weights into regs (overlaps compute)
        if (it < 107) {
            int it2 = it + 1; int cb2 = it2 / 27; int t2 = it2 - cb2 * 27;
            const uint4* srcH = (const uint4*)(g_wh + (size_t)(sel * 27 + t2) * 16384);
            const uint4* srcL = (const uint4*)(g_wl + (size_t)(sel * 27 + t2) * 16384);
#pragma unroll
            for (int r = 0; r < 4; r++) {
                int idx = tid + 256 * r; int isl = idx >> 9; int lin = idx & 511;
                int oc = lin >> 2, q = lin & 3;
                const uint4* s = isl ? srcL : srcH;
                wr[r] = s[oc * 16 + cb2 * 4 + q];
            }
        }
        // compute tap t from buffer it&1
        {
            int buf = it & 1;
            int a = t / 9; int rem9 = t - a * 9;
            int bj = rem9 / 3; int cc = rem9 - bj * 3;
            int r15 = lane & 15;
            uint32_t rowoff = (uint32_t)((((a * 6 + jl + bj) * 34) + (k0 + r15 + cc)) * (XP * 2));
            uint32_t csel = (uint32_t)((lane >> 4) * 16);
            uint32_t aH = xs_h_u + rowoff + csel;
            uint32_t aL = xs_l_u + rowoff + csel;
            uint32_t Ah0[4], Ah1[4], Al0[4], Al1[4];
            ldsm4(Ah0, aH); ldsm4(Ah1, aH + 32);
            ldsm4(Al0, aL); ldsm4(Al1, aL + 32);
            uint32_t whb = wb_u + (uint32_t)(buf * 2 * 128 * XP * 2);
            uint32_t wlb = whb + (uint32_t)(128 * XP * 2);
            int rowB = (lane & 7) + ((lane >> 4) << 3);
            int colB = ((lane >> 3) & 1) * 16;
#pragma unroll
            for (int np = 0; np < 8; np++) {
                uint32_t bo0 = (uint32_t)(((np * 16 + rowB) * XP) * 2 + colB);
#pragma unroll
                for (int ks = 0; ks < 2; ks++) {
                    uint32_t off = bo0 + ks * 32;
                    uint32_t Bh[4], Bl[4];
                    ldsm4(Bh, whb + off);
                    ldsm4(Bl, wlb + off);
                    const uint32_t* A0 = ks ? Ah1 : Ah0;
                    const uint32_t* A1 = ks ? Al1 : Al0;
                    mma_bf16(acc[np * 2],     A0, Bh[0], Bh[1]);
                    mma_bf16(acc[np * 2],     A0, Bl[0], Bl[1]);
                    mma_bf16(acc[np * 2],     A1, Bh[0], Bh[1]);
                    mma_bf16(acc[np * 2 + 1], A0, Bh[2], Bh[3]);
                    mma_bf16(acc[np * 2 + 1], A0, Bl[2], Bl[3]);
                    mma_bf16(acc[np * 2 + 1], A1, Bh[2], Bh[3]);
                }
            }
        }
    }

    // epilogue: acc + bias -> out (fp32)
    int gi = blockIdx.y, gj = blockIdx.x * 4 + jl;
    int tok0 = (gi << 10) + (gj << 5) + k0 + (lane >> 2);
#pragma unroll
    for (int nt = 0; nt < 16; nt++) {
        int col = nt * 8 + (lane & 3) * 2;
        float b0 = bias_s[col], b1 = bias_s[col + 1];
        float2 v0 = make_float2(acc[nt][0] + b0, acc[nt][1] + b1);
        float2 v1 = make_float2(acc[nt][2] + b0, acc[nt][3] + b1);
        *(float2*)&out[tok0 * 128 + col] = v0;
        *(float2*)&out[(tok0 + 8) * 128 + col] = v1;
    }
}

// ---------------- zero slice accumulators ----------------
__global__ void k_zero() {
    int t = threadIdx.x;
    g_norm[t] = 0.0f;
    for (int i = t; i < 4096; i += 256) g_toknum[i] = 0.0f;
}

// ---------------- slice softmax + N-reductions ----------------
__global__ void __launch_bounds__(256) k_slice(
    const float* __restrict__ sw, const float* __restrict__ sb,
    const float* __restrict__ temp)
{
    __shared__ float sw_s[512];
    __shared__ float sb_s[32];
    __shared__ float xm_s[8 * 128];
    __shared__ float fx_s[8 * 128];
    int tid = threadIdx.x;
    int h = tid >> 5;
    int g = tid & 31;
    for (int i = tid; i < 512; i += 256) sw_s[i] = sw[i];
    if (tid < 32) sb_s[tid] = sb[tid];
    float invt = 1.0f / temp[h];
    float nacc = 0.0f;
    float tacc[16];
#pragma unroll
    for (int d = 0; d < 16; d++) tacc[d] = 0.0f;
    int tok0 = blockIdx.x * 256;

    for (int bt = 0; bt < 32; bt++) {
        __syncthreads();
        int tb = tok0 + bt * 8;
        for (int i = tid; i < 1024; i += 256) {
            int t = i >> 7, c = i & 127;
            xm_s[i] = g_xmid[(tb + t) * 128 + c];
            fx_s[i] = g_fxmid[(tb + t) * 128 + c];
        }
        __syncthreads();
#pragma unroll 1
        for (int t = 0; t < 8; t++) {
            float lg = sb_s[g];
#pragma unroll
            for (int d = 0; d < 16; d++) lg += xm_s[t * 128 + h * 16 + d] * sw_s[d * 32 + g];
            lg *= invt;
            float m = warp_max(lg);
            float e = expf(lg - m);
            float s = warp_sum(e);
            float w = e / s;
            g_swt[(tb + t) * 256 + tid] = w;
            nacc += w;
#pragma unroll
            for (int d = 0; d < 16; d++) tacc[d] += fx_s[t * 128 + h * 16 + d] * w;
        }
    }
    atomicAdd(&g_norm[tid], nacc);
#pragma unroll
    for (int d = 0; d < 16; d++) atomicAdd(&g_toknum[tid * 16 + d], tacc[d]);
}

// ---------------- tiny slice attention (1 block, 256 threads) ----------------
__global__ void __launch_bounds__(256) k_attn(
    const float* __restrict__ wq, const float* __restrict__ wk,
    const float* __restrict__ wv)
{
    __shared__ float k_s[4096];
    __shared__ float v_s[4096];
    int tid = threadIdx.x;
    int h = tid >> 5;
    float tokr[16];
    float nrm = g_norm[tid] + 1e-5f;
#pragma unroll
    for (int d = 0; d < 16; d++) tokr[d] = g_toknum[tid * 16 + d] / nrm;
    float q[16];
#pragma unroll
    for (int dd = 0; dd < 16; dd++) {
        float aq = 0.f, ak = 0.f, av = 0.f;
#pragma unroll
        for (int d = 0; d < 16; d++) {
            aq += tokr[d] * wq[d * 16 + dd];
            ak += tokr[d] * wk[d * 16 + dd];
            av += tokr[d] * wv[d * 16 + dd];
        }
        q[dd] = aq;
        k_s[tid * 16 + dd] = ak;
        v_s[tid * 16 + dd] = av;
    }
    __syncthreads();
    float p[32];
    float mx = -1e30f;
#pragma unroll 1
    for (int g2 = 0; g2 < 32; g2++) {
        float s = 0.f;
#pragma unroll
        for (int d = 0; d < 16; d++) s += q[d] * k_s[(h * 32 + g2) * 16 + d];
        s *= 0.25f;
        p[g2] = s;
        mx = fmaxf(mx, s);
    }
    float sum = 0.f;
#pragma unroll
    for (int g2 = 0; g2 < 32; g2++) { p[g2] = expf(p[g2] - mx); sum += p[g2]; }
    float inv = 1.0f / sum;
#pragma unroll 1
    for (int c = 0; c < 16; c++) {
        float o = 0.f;
#pragma unroll
        for (int g2 = 0; g2 < 32; g2++) o += p[g2] * v_s[(h * 32 + g2) * 16 + c];
        g_ot[tid * 16 + c] = o * inv;
    }
}

// ---------------- de-slice + wo projection + residual ----------------
__global__ void __launch_bounds__(128) k_deslice(
    const float* __restrict__ wo, const float* __restrict__ bo)
{
    __shared__ float swt_s[16 * 256];
    __shared__ float tmp_s[16 * 128];
    int tid = threadIdx.x;
    int tok0 = blockIdx.x * 16;
    for (int i = tid; i < 4096; i += 128) swt_s[i] = g_swt[tok0 * 256 + i];
    __syncthreads();
    {
        int c = tid, h = c >> 4, cc = c & 15;
        float acc[16];
#pragma unroll
        for (int t = 0; t < 16; t++) acc[t] = 0.0f;
        for (int g = 0; g < 32; g++) {
            float ov = g_ot[(h * 32 + g) * 16 + cc];
#pragma unroll
            for (int t = 0; t < 16; t++) acc[t] += swt_s[t * 256 + h * 32 + g] * ov;
        }
#pragma unroll
        for (int t = 0; t < 16; t++) tmp_s[t * 128 + c] = acc[t];
    }
    __syncthreads();
    {
        int o = tid;
        float facc[16];
#pragma unroll
        for (int t = 0; t < 16; t++) facc[t] = 0.0f;
        for (int m4 = 0; m4 < 32; m4++) {
            int m = m4 * 4;
            float w0 = wo[(m + 0) * 128 + o], w1 = wo[(m + 1) * 128 + o];
            float w2 = wo[(m + 2) * 128 + o], w3 = wo[(m + 3) * 128 + o];
#pragma unroll
            for (int t = 0; t < 16; t++) {
                float4 v = ((const float4*)tmp_s)[t * 32 + m4];
                facc[t] += v.x * w0 + v.y * w1 + v.z * w2 + v.w * w3;
            }
        }
        float bv = bo[o];
#pragma unroll
        for (int t = 0; t < 16; t++) g_z[(tok0 + t) * 128 + o] += facc[t] + bv;
    }
}

// ---------------- MLP: z += gelu(zn@W1+b1)@W2+b2 ----------------
__global__ void __launch_bounds__(128) k_mlp(
    const float* __restrict__ W1, const float* __restrict__ b1,
    const float* __restrict__ W2, const float* __restrict__ b2)
{
    __shared__ float zn_s[32 * 128];
    __shared__ float mid_s[32 * 128];
    int tid = threadIdx.x;
    int tok0 = blockIdx.x * 32;
    for (int i = tid; i < 4096; i += 128) zn_s[i] = g_zn[tok0 * 128 + i];
    __syncthreads();
    {
        float acc[32];
#pragma unroll
        for (int t = 0; t < 32; t++) acc[t] = 0.0f;
        for (int c4 = 0; c4 < 32; c4++) {
            int c = c4 * 4;
            float w0 = W1[(c + 0) * 128 + tid], w1 = W1[(c + 1) * 128 + tid];
            float w2 = W1[(c + 2) * 128 + tid], w3 = W1[(c + 3) * 128 + tid];
#pragma unroll
            for (int t = 0; t < 32; t++) {
                float4 v = ((const float4*)zn_s)[t * 32 + c4];
                acc[t] += v.x * w0 + v.y * w1 + v.z * w2 + v.w * w3;
            }
        }
        float bb = b1[tid];
#pragma unroll
        for (int t = 0; t < 32; t++) mid_s[t * 128 + tid] = gelu_exact(acc[t] + bb);
    }
    __syncthreads();
    {
        float acc[32];
#pragma unroll
        for (int t = 0; t < 32; t++) acc[t] = 0.0f;
        for (int m4 = 0; m4 < 32; m4++) {
            int m = m4 * 4;
            float w0 = W2[(m + 0) * 128 + tid], w1 = W2[(m + 1) * 128 + tid];
            float w2 = W2[(m + 2) * 128 + tid], w3 = W2[(m + 3) * 128 + tid];
#pragma unroll
            for (int t = 0; t < 32; t++) {
                float4 v = ((const float4*)mid_s)[t * 32 + m4];
                acc[t] += v.x * w0 + v.y * w1 + v.z * w2 + v.w * w3;
            }
        }
        float bb = b2[tid];
#pragma unroll
        for (int t = 0; t < 32; t++) g_z[(tok0 + t) * 128 + tid] += acc[t] + bb;
    }
}

// ---------------- final LN + head ----------------
__global__ void __launch_bounds__(256) k_final(
    const float* __restrict__ g, const float* __restrict__ b,
    const float* __restrict__ ow, const float* __restrict__ ob,
    float* __restrict__ out)
{
    int warp = threadIdx.x >> 5, lane = threadIdx.x & 31;
    int n = blockIdx.x * 8 + warp;
    float4 v = ((const float4*)g_z)[n * 32 + lane];
    float s = warp_sum(v.x + v.y + v.z + v.w);
    float mu = s * (1.0f / 128.0f);
    float q = warp_sum(v.x * v.x + v.y * v.y + v.z * v.z + v.w * v.w);
    float var = q * (1.0f / 128.0f) - mu * mu;
    float inv = rsqrtf(var + 1e-5f);
    float4 gg = ((const float4*)g)[lane];
    float4 bb = ((const float4*)b)[lane];
    float4 w4 = ((const float4*)ow)[lane];
    float y0 = (v.x - mu) * inv * gg.x + bb.x;
    float y1 = (v.y - mu) * inv * gg.y + bb.y;
    float y2 = (v.z - mu) * inv * gg.z + bb.z;
    float y3 = (v.w - mu) * inv * gg.w + bb.w;
    float p = warp_sum(y0 * w4.x + y1 * w4.y + y2 * w4.z + y3 * w4.w);
    if (lane == 0) out[n] = p + ob[0];
}

// ---------------- host launch ----------------
extern "C" void kernel_launch(void* const* d_in, const int* in_sizes, int n_in,
                              void* d_out, int out_size)
{
    const float* x        = (const float*)d_in[0];
    const float* fx       = (const float*)d_in[1];
    const float* pre_w1   = (const float*)d_in[2];
    const float* pre_b1   = (const float*)d_in[3];
    const float* pre_w2   = (const float*)d_in[4];
    const float* pre_b2   = (const float*)d_in[5];
    const float* place    = (const float*)d_in[6];
    const float* ln1_g    = (const float*)d_in[7];
    const float* ln1_b    = (const float*)d_in[8];
    const float* convx_w  = (const float*)d_in[9];
    const float* convx_b  = (const float*)d_in[10];
    const float* convfx_w = (const float*)d_in[11];
    const float* convfx_b = (const float*)d_in[12];
    const float* slice_w  = (const float*)d_in[13];
    const float* slice_b  = (const float*)d_in[14];
    const float* temp     = (const float*)d_in[15];
    const float* wq       = (const float*)d_in[16];
    const float* wk       = (const float*)d_in[17];
    const float* wv       = (const float*)d_in[18];
    const float* wo       = (const float*)d_in[19];
    const float* bo       = (const float*)d_in[20];
    const float* ln2_g    = (const float*)d_in[21];
    const float* ln2_b    = (const float*)d_in[22];
    const float* mlp_w1   = (const float*)d_in[23];
    const float* mlp_b1   = (const float*)d_in[24];
    const float* mlp_w2   = (const float*)d_in[25];
    const float* mlp_b2   = (const float*)d_in[26];
    const float* ln3_g    = (const float*)d_in[27];
    const float* ln3_b    = (const float*)d_in[28];
    const float* out_w    = (const float*)d_in[29];
    const float* out_b    = (const float*)d_in[30];
    float* out = (float*)d_out;

    cudaFuncSetAttribute(k_conv_mma,
                         cudaFuncAttributeMaxDynamicSharedMemorySize, CONV_SMEM);

    k_cvt_w<<<dim3(1728, 4), 256>>>(convx_w, convfx_w);
    k_pre<<<NTOK / 32, 128>>>(x, fx, pre_w1, pre_b1, pre_w2, pre_b2, place);

    for (int l = 0; l < 2; l++) {
        k_ln<<<NTOK / 8, 256>>>(ln1_g + l * 128, ln1_b + l * 128);
        k_conv_mma<<<dim3(8, 32, 2), 256, CONV_SMEM>>>(
            convx_b + l * 128, convfx_b + l * 128, l);
        k_zero<<<1, 256>>>();
        k_slice<<<128, 256>>>(slice_w + l * 512, slice_b + l * 32, temp + l * 8);
        k_attn<<<1, 256>>>(wq + l * 256, wk + l * 256, wv + l * 256);
        k_deslice<<<NTOK / 16, 128>>>(wo + l * 16384, bo + l * 128);
        k_ln<<<NTOK / 8, 256>>>(ln2_g + l * 128, ln2_b + l * 128);
        k_mlp<<<NTOK / 32, 128>>>(mlp_w1 + l * 16384, mlp_b1 + l * 128,
                                  mlp_w2 + l * 16384, mlp_b2 + l * 128);
    }
    k_final<<<NTOK / 8, 256>>>(ln3_g, ln3_b, out_w, out_b, out);
}

// round 14
// speedup vs baseline: 3.2882x; 1.1379x over previous
#include <cuda_runtime.h>
#include <cuda_bf16.h>
#include <math.h>
#include <stdint.h>

#define NTOK 32768
#define C 128
#define XP 40   // bf16 pitch for ic dimension (conflict-free ldmatrix)

// ---------------- device scratch (no allocations allowed) ----------------
__device__ float g_z[NTOK * C];      // residual stream
__device__ float g_zn[NTOK * C];     // LN output (fp32)
__device__ float g_xmid[NTOK * C];   // conv-x output
__device__ float g_fxmid[NTOK * C];  // conv-fx output
__device__ float g_swt[NTOK * 256];  // slice weights [n][h][g]
__device__ float g_norm[256];        // [h][g]
__device__ float g_toknum[4096];     // [h][g][dh]
__device__ float g_ot[4096];         // [h][g][dh]
__device__ __nv_bfloat16 g_znh[NTOK * C];       // LN output hi (bf16)
__device__ __nv_bfloat16 g_znl[NTOK * C];       // LN output lo (bf16)
// conv weights in mma B-fragment order:
// [sel][tap][kc(8 = 128ic/16)][npg(8)][lane(32)] -> uint4 = regs (m0,m1,m2,m3)
__device__ uint4 g_wfh[4 * 27 * 8 * 8 * 32];
__device__ uint4 g_wfl[4 * 27 * 8 * 8 * 32];

__device__ __forceinline__ float gelu_exact(float v) {
    return 0.5f * v * (1.0f + erff(v * 0.70710678118654752f));
}

__device__ __forceinline__ float warp_sum(float s) {
#pragma unroll
    for (int o = 16; o; o >>= 1) s += __shfl_xor_sync(0xffffffffu, s, o);
    return s;
}
__device__ __forceinline__ float warp_max(float s) {
#pragma unroll
    for (int o = 16; o; o >>= 1) s = fmaxf(s, __shfl_xor_sync(0xffffffffu, s, o));
    return s;
}

__device__ __forceinline__ void ldsm4(uint32_t* r, uint32_t addr) {
    asm volatile("ldmatrix.sync.aligned.m8n8.x4.shared.b16 {%0,%1,%2,%3}, [%4];"
        : "=r"(r[0]), "=r"(r[1]), "=r"(r[2]), "=r"(r[3]) : "r"(addr));
}
__device__ __forceinline__ void mma_bf16(float* d, const uint32_t* a,
                                         uint32_t b0, uint32_t b1) {
    asm volatile(
        "mma.sync.aligned.m16n8k16.row.col.f32.bf16.bf16.f32 "
        "{%0,%1,%2,%3}, {%4,%5,%6,%7}, {%8,%9}, {%0,%1,%2,%3};"
        : "+f"(d[0]), "+f"(d[1]), "+f"(d[2]), "+f"(d[3])
        : "r"(a[0]), "r"(a[1]), "r"(a[2]), "r"(a[3]), "r"(b0), "r"(b1));
}

// ---------------- weight conversion: fp32 [oc][ic][tap] -> B-fragment uint4 ----------
// One thread per uint4; 221184 total -> 864 blocks of 256.
// kc indexes the 16-wide k (ic) slice: ic = kc*16 + ...
// Fragment mapping (matches mma m16n8k16 B col-major requirement):
//   b-reg element for lane l: oc = npg*16 + l/4 (+8 for m2/m3),
//   ic = kc*16 + 2*(l&3) (+1 in high half, +8 for m1/m3).
__global__ void __launch_bounds__(256) k_cvt_frag(
    const float* __restrict__ wx, const float* __restrict__ wf)
{
    int idx = blockIdx.x * 256 + threadIdx.x;   // < 221184
    int lane = idx & 31;
    int npg = (idx >> 5) & 7;
    int kc = (idx >> 8) & 7;
    int rest = idx >> 11;       // sel*27 + tap, 0..107
    int tap = rest % 27;
    int sel = rest / 27;
    const float* src = ((sel & 1) ? wf : wx) + (sel >> 1) * 442368;
    int oc0 = npg * 16 + (lane >> 2);
    int k0 = kc * 16 + 2 * (lane & 3);
    uint32_t h[4], l[4];
#pragma unroll
    for (int m = 0; m < 4; m++) {
        int oc = oc0 + ((m >> 1) << 3);
        int kk = k0 + ((m & 1) << 3);
        float v0 = src[(oc * 128 + kk) * 27 + tap];
        float v1 = src[(oc * 128 + kk + 1) * 27 + tap];
        __nv_bfloat16 h0 = __float2bfloat16(v0), h1 = __float2bfloat16(v1);
        float r0 = v0 - __bfloat162float(h0), r1 = v1 - __bfloat162float(h1);
        __nv_bfloat16 l0 = __float2bfloat16(r0), l1 = __float2bfloat16(r1);
        h[m] = (uint32_t)__bfloat16_as_ushort(h0) |
               ((uint32_t)__bfloat16_as_ushort(h1) << 16);
        l[m] = (uint32_t)__bfloat16_as_ushort(l0) |
               ((uint32_t)__bfloat16_as_ushort(l1) << 16);
    }
    g_wfh[idx] = make_uint4(h[0], h[1], h[2], h[3]);
    g_wfl[idx] = make_uint4(l[0], l[1], l[2], l[3]);
}

// ---------------- pre-MLP: z = gelu(h@W1+b1)@W2+b2+placeholder ----------------
__global__ void __launch_bounds__(128) k_pre(
    const float* __restrict__ x, const float* __restrict__ fx,
    const float* __restrict__ W1, const float* __restrict__ b1,
    const float* __restrict__ W2, const float* __restrict__ b2,
    const float* __restrict__ ph)
{
    __shared__ float h_s[32 * 4];
    __shared__ float mid_s[32 * 256];
    int tid = threadIdx.x;
    int tok0 = blockIdx.x * 32;

    for (int i = tid; i < 128; i += 128) {
        int t = i >> 2, j = i & 3;
        h_s[i] = (j < 3) ? x[(tok0 + t) * 3 + j] : fx[tok0 + t];
    }
    __syncthreads();

#pragma unroll
    for (int rep = 0; rep < 2; rep++) {
        int m = tid + rep * 128;
        float w0 = W1[0 * 256 + m], w1 = W1[1 * 256 + m];
        float w2 = W1[2 * 256 + m], w3 = W1[3 * 256 + m];
        float bb = b1[m];
#pragma unroll
        for (int t = 0; t < 32; t++) {
            float4 hv = ((const float4*)h_s)[t];
            float v = bb + hv.x * w0 + hv.y * w1 + hv.z * w2 + hv.w * w3;
            mid_s[t * 256 + m] = gelu_exact(v);
        }
    }
    __syncthreads();

    int o = tid;
    float acc[32];
#pragma unroll
    for (int t = 0; t < 32; t++) acc[t] = 0.0f;
    for (int m4 = 0; m4 < 64; m4++) {
        int m = m4 * 4;
        float w0 = W2[(m + 0) * 128 + o], w1 = W2[(m + 1) * 128 + o];
        float w2 = W2[(m + 2) * 128 + o], w3 = W2[(m + 3) * 128 + o];
#pragma unroll
        for (int t = 0; t < 32; t++) {
            float4 v = ((const float4*)mid_s)[t * 64 + m4];
            acc[t] += v.x * w0 + v.y * w1 + v.z * w2 + v.w * w3;
        }
    }
    float bb = b2[o] + ph[o];
#pragma unroll
    for (int t = 0; t < 32; t++) g_z[(tok0 + t) * 128 + o] = acc[t] + bb;
}

// ---------------- LayerNorm: zn = LN(z)*g+b (fp32 + bf16 hi/lo) ----------------
__global__ void __launch_bounds__(256) k_ln(
    const float* __restrict__ g, const float* __restrict__ b)
{
    int warp = threadIdx.x >> 5, lane = threadIdx.x & 31;
    int n = blockIdx.x * 8 + warp;
    float4 v = ((const float4*)g_z)[n * 32 + lane];
    float s = warp_sum(v.x + v.y + v.z + v.w);
    float mu = s * (1.0f / 128.0f);
    float q = warp_sum(v.x * v.x + v.y * v.y + v.z * v.z + v.w * v.w);
    float var = q * (1.0f / 128.0f) - mu * mu;
    float inv = rsqrtf(var + 1e-5f);
    float4 gg = ((const float4*)g)[lane];
    float4 bb = ((const float4*)b)[lane];
    float4 y;
    y.x = (v.x - mu) * inv * gg.x + bb.x;
    y.y = (v.y - mu) * inv * gg.y + bb.y;
    y.z = (v.z - mu) * inv * gg.z + bb.z;
    y.w = (v.w - mu) * inv * gg.w + bb.w;
    ((float4*)g_zn)[n * 32 + lane] = y;
    // bf16 hi/lo for the tensor-core conv
    __nv_bfloat162 h0, h1, l0, l1;
    h0.x = __float2bfloat16(y.x); l0.x = __float2bfloat16(y.x - __bfloat162float(h0.x));
    h0.y = __float2bfloat16(y.y); l0.y = __float2bfloat16(y.y - __bfloat162float(h0.y));
    h1.x = __float2bfloat16(y.z); l1.x = __float2bfloat16(y.z - __bfloat162float(h1.x));
    h1.y = __float2bfloat16(y.w); l1.y = __float2bfloat16(y.w - __bfloat162float(h1.y));
    ((__nv_bfloat162*)g_znh)[n * 64 + lane * 2 + 0] = h0;
    ((__nv_bfloat162*)g_znh)[n * 64 + lane * 2 + 1] = h1;
    ((__nv_bfloat162*)g_znl)[n * 64 + lane * 2 + 0] = l0;
    ((__nv_bfloat162*)g_znl)[n * 64 + lane * 2 + 1] = l1;
}

// ---------------- conv3d 3x3x3 via bf16 split tensor cores (fragment-LDG B) --------
// grid (8 j-tiles, 32 i, 2 conv). Block 256 thr = 8 warps, 2 CTAs/SM.
// Block tile: 128 tokens (fixed i, 4 j, 32 k) x 128 oc.
// Warp tile: 32 tokens (one j line) x 64 oc. B fragments loaded directly from
// gmem (pre-swizzled, L1/L2 resident) -> no weight smem, no per-tap syncs.
// 3 mma terms: Ah*Bh + Ah*Bl + Al*Bh  (drop lo*lo, err ~2^-16).
#define CONV_SMEM (2 * 612 * XP * 2 + 512)
__global__ void __launch_bounds__(256, 2) k_conv_mma(
    const float* __restrict__ bx, const float* __restrict__ bf, int layer)
{
    extern __shared__ char sm_raw[];
    float* bias_s = (float*)(sm_raw + 2 * 612 * XP * 2);

    const int tid = threadIdx.x, lane = tid & 31, warp = tid >> 5;
    const int z = blockIdx.z;
    const int sel = layer * 2 + z;
    const float* bias = z ? bf : bx;
    float* out = z ? g_fxmid : g_xmid;
    const int tg = warp >> 1;   // j-line 0..3 (32 tokens)
    const int og = warp & 1;    // oc half: og*64

    uint32_t su = (uint32_t)__cvta_generic_to_shared(sm_raw);
    const uint32_t xs_h_u = su;
    const uint32_t xs_l_u = su + 612 * XP * 2;

    if (tid < 128) bias_s[tid] = bias[tid];

    const uint4* __restrict__ wfh = g_wfh + sel * 55296;
    const uint4* __restrict__ wfl = g_wfl + sel * 55296;

    float acc[16][4];   // [mg*8 + np*2 + h][reg]
#pragma unroll
    for (int n = 0; n < 16; n++) {
        acc[n][0] = acc[n][1] = acc[n][2] = acc[n][3] = 0.f;
    }

    const int r15 = lane & 15;
    const int csel = (lane >> 4) * 16;

    for (int cb = 0; cb < 4; cb++) {
        __syncthreads();
        // stage halo neighborhood (3x6x34 positions x 32 ic) hi+lo
        for (int idx = tid; idx < 4896; idx += 256) {
            int arr = idx >= 2448;
            int lin = arr ? idx - 2448 : idx;
            int pos = lin >> 2, q = lin & 3;
            int ii = pos / 204; int rem = pos - ii * 204;
            int jj = rem / 34;  int kk = rem - jj * 34;
            int gi = (int)blockIdx.y + ii - 1;
            int gj = (int)blockIdx.x * 4 + jj - 1;
            int gk = kk - 1;
            uint4 v = make_uint4(0u, 0u, 0u, 0u);
            if ((unsigned)gi < 32u && (unsigned)gj < 32u && (unsigned)gk < 32u) {
                int tokn = (gi << 10) + (gj << 5) + gk;
                const uint4* srcp = arr ? (const uint4*)g_znl : (const uint4*)g_znh;
                v = srcp[tokn * 16 + cb * 4 + q];
            }
            char* dst = sm_raw + (size_t)arr * (612 * XP * 2) + pos * (XP * 2) + q * 16;
            *(uint4*)dst = v;
        }
        __syncthreads();

#pragma unroll 1
        for (int t = 0; t < 27; t++) {
            int a = t / 9; int rem9 = t - a * 9;
            int bj = rem9 / 3; int cc = rem9 - bj * 3;
            int lineoff = (a * 6 + tg + bj) * 34;
#pragma unroll
            for (int ks = 0; ks < 2; ks++) {
                int kci = cb * 2 + ks;   // 16-wide k slice within the full 128 ic
                uint32_t off0 = (uint32_t)((lineoff + r15 + cc) * (XP * 2))
                                + csel + ks * 32;
                uint32_t off1 = off0 + 16 * (XP * 2);
                uint32_t Ah0[4], Ah1[4], Al0[4], Al1[4];
                ldsm4(Ah0, xs_h_u + off0);
                ldsm4(Ah1, xs_h_u + off1);
                ldsm4(Al0, xs_l_u + off0);
                ldsm4(Al1, xs_l_u + off1);
                const uint4* bh = wfh + ((t * 8 + kci) * 8 + og * 4) * 32 + lane;
                const uint4* bl = wfl + ((t * 8 + kci) * 8 + og * 4) * 32 + lane;
#pragma unroll
                for (int np = 0; np < 4; np++) {
                    uint4 Bh = bh[np * 32];
                    uint4 Bl = bl[np * 32];
                    mma_bf16(acc[np * 2 + 0], Ah0, Bh.x, Bh.y);
                    mma_bf16(acc[np * 2 + 0], Ah0, Bl.x, Bl.y);
                    mma_bf16(acc[np * 2 + 0], Al0, Bh.x, Bh.y);
                    mma_bf16(acc[np * 2 + 1], Ah0, Bh.z, Bh.w);
                    mma_bf16(acc[np * 2 + 1], Ah0, Bl.z, Bl.w);
                    mma_bf16(acc[np * 2 + 1], Al0, Bh.z, Bh.w);
                    mma_bf16(acc[8 + np * 2 + 0], Ah1, Bh.x, Bh.y);
                    mma_bf16(acc[8 + np * 2 + 0], Ah1, Bl.x, Bl.y);
                    mma_bf16(acc[8 + np * 2 + 0], Al1, Bh.x, Bh.y);
                    mma_bf16(acc[8 + np * 2 + 1], Ah1, Bh.z, Bh.w);
                    mma_bf16(acc[8 + np * 2 + 1], Ah1, Bl.z, Bl.w);
                    mma_bf16(acc[8 + np * 2 + 1], Al1, Bh.z, Bh.w);
                }
            }
        }
    }

    // epilogue: acc + bias -> out (fp32)
    int gi = blockIdx.y, gj = blockIdx.x * 4 + tg;
    int base_tok = (gi << 10) + (gj << 5);
#pragma unroll
    for (int mg = 0; mg < 2; mg++) {
#pragma unroll
        for (int np = 0; np < 4; np++) {
#pragma unroll
            for (int h = 0; h < 2; h++) {
                float* a = acc[mg * 8 + np * 2 + h];
                int col = og * 64 + np * 16 + h * 8 + (lane & 3) * 2;
                int tk = base_tok + mg * 16 + (lane >> 2);
                float b0 = bias_s[col], b1 = bias_s[col + 1];
                *(float2*)&out[tk * 128 + col] = make_float2(a[0] + b0, a[1] + b1);
                *(float2*)&out[(tk + 8) * 128 + col] = make_float2(a[2] + b0, a[3] + b1);
            }
        }
    }
}

// ---------------- zero slice accumulators ----------------
__global__ void k_zero() {
    int t = threadIdx.x;
    g_norm[t] = 0.0f;
    for (int i = t; i < 4096; i += 256) g_toknum[i] = 0.0f;
}

// ---------------- slice softmax + N-reductions ----------------
__global__ void __launch_bounds__(256) k_slice(
    const float* __restrict__ sw, const float* __restrict__ sb,
    const float* __restrict__ temp)
{
    __shared__ float sw_s[512];
    __shared__ float sb_s[32];
    __shared__ float xm_s[8 * 128];
    __shared__ float fx_s[8 * 128];
    int tid = threadIdx.x;
    int h = tid >> 5;
    int g = tid & 31;
    for (int i = tid; i < 512; i += 256) sw_s[i] = sw[i];
    if (tid < 32) sb_s[tid] = sb[tid];
    float invt = 1.0f / temp[h];
    float nacc = 0.0f;
    float tacc[16];
#pragma unroll
    for (int d = 0; d < 16; d++) tacc[d] = 0.0f;
    int tok0 = blockIdx.x * 256;

    for (int bt = 0; bt < 32; bt++) {
        __syncthreads();
        int tb = tok0 + bt * 8;
        for (int i = tid; i < 1024; i += 256) {
            int t = i >> 7, c = i & 127;
            xm_s[i] = g_xmid[(tb + t) * 128 + c];
            fx_s[i] = g_fxmid[(tb + t) * 128 + c];
        }
        __syncthreads();
#pragma unroll 1
        for (int t = 0; t < 8; t++) {
            float lg = sb_s[g];
#pragma unroll
            for (int d = 0; d < 16; d++) lg += xm_s[t * 128 + h * 16 + d] * sw_s[d * 32 + g];
            lg *= invt;
            float m = warp_max(lg);
            float e = expf(lg - m);
            float s = warp_sum(e);
            float w = e / s;
            g_swt[(tb + t) * 256 + tid] = w;
            nacc += w;
#pragma unroll
            for (int d = 0; d < 16; d++) tacc[d] += fx_s[t * 128 + h * 16 + d] * w;
        }
    }
    atomicAdd(&g_norm[tid], nacc);
#pragma unroll
    for (int d = 0; d < 16; d++) atomicAdd(&g_toknum[tid * 16 + d], tacc[d]);
}

// ---------------- tiny slice attention (1 block, 256 threads) ----------------
__global__ void __launch_bounds__(256) k_attn(
    const float* __restrict__ wq, const float* __restrict__ wk,
    const float* __restrict__ wv)
{
    __shared__ float k_s[4096];
    __shared__ float v_s[4096];
    int tid = threadIdx.x;
    int h = tid >> 5;
    float tokr[16];
    float nrm = g_norm[tid] + 1e-5f;
#pragma unroll
    for (int d = 0; d < 16; d++) tokr[d] = g_toknum[tid * 16 + d] / nrm;
    float q[16];
#pragma unroll
    for (int dd = 0; dd < 16; dd++) {
        float aq = 0.f, ak = 0.f, av = 0.f;
#pragma unroll
        for (int d = 0; d < 16; d++) {
            aq += tokr[d] * wq[d * 16 + dd];
            ak += tokr[d] * wk[d * 16 + dd];
            av += tokr[d] * wv[d * 16 + dd];
        }
        q[dd] = aq;
        k_s[tid * 16 + dd] = ak;
        v_s[tid * 16 + dd] = av;
    }
    __syncthreads();
    float p[32];
    float mx = -1e30f;
#pragma unroll 1
    for (int g2 = 0; g2 < 32; g2++) {
        float s = 0.f;
#pragma unroll
        for (int d = 0; d < 16; d++) s += q[d] * k_s[(h * 32 + g2) * 16 + d];
        s *= 0.25f;
        p[g2] = s;
        mx = fmaxf(mx, s);
    }
    float sum = 0.f;
#pragma unroll
    for (int g2 = 0; g2 < 32; g2++) { p[g2] = expf(p[g2] - mx); sum += p[g2]; }
    float inv = 1.0f / sum;
#pragma unroll 1
    for (int c = 0; c < 16; c++) {
        float o = 0.f;
#pragma unroll
        for (int g2 = 0; g2 < 32; g2++) o += p[g2] * v_s[(h * 32 + g2) * 16 + c];
        g_ot[tid * 16 + c] = o * inv;
    }
}

// ---------------- de-slice + wo projection + residual ----------------
__global__ void __launch_bounds__(128) k_deslice(
    const float* __restrict__ wo, const float* __restrict__ bo)
{
    __shared__ float swt_s[16 * 256];
    __shared__ float tmp_s[16 * 128];
    int tid = threadIdx.x;
    int tok0 = blockIdx.x * 16;
    for (int i = tid; i < 4096; i += 128) swt_s[i] = g_swt[tok0 * 256 + i];
    __syncthreads();
    {
        int c = tid, h = c >> 4, cc = c & 15;
        float acc[16];
#pragma unroll
        for (int t = 0; t < 16; t++) acc[t] = 0.0f;
        for (int g = 0; g < 32; g++) {
            float ov = g_ot[(h * 32 + g) * 16 + cc];
#pragma unroll
            for (int t = 0; t < 16; t++) acc[t] += swt_s[t * 256 + h * 32 + g] * ov;
        }
#pragma unroll
        for (int t = 0; t < 16; t++) tmp_s[t * 128 + c] = acc[t];
    }
    __syncthreads();
    {
        int o = tid;
        float facc[16];
#pragma unroll
        for (int t = 0; t < 16; t++) facc[t] = 0.0f;
        for (int m4 = 0; m4 < 32; m4++) {
            int m = m4 * 4;
            float w0 = wo[(m + 0) * 128 + o], w1 = wo[(m + 1) * 128 + o];
            float w2 = wo[(m + 2) * 128 + o], w3 = wo[(m + 3) * 128 + o];
#pragma unroll
            for (int t = 0; t < 16; t++) {
                float4 v = ((const float4*)tmp_s)[t * 32 + m4];
                facc[t] += v.x * w0 + v.y * w1 + v.z * w2 + v.w * w3;
            }
        }
        float bv = bo[o];
#pragma unroll
        for (int t = 0; t < 16; t++) g_z[(tok0 + t) * 128 + o] += facc[t] + bv;
    }
}

// ---------------- MLP: z += gelu(zn@W1+b1)@W2+b2 ----------------
__global__ void __launch_bounds__(128) k_mlp(
    const float* __restrict__ W1, const float* __restrict__ b1,
    const float* __restrict__ W2, const float* __restrict__ b2)
{
    __shared__ float zn_s[32 * 128];
    __shared__ float mid_s[32 * 128];
    int tid = threadIdx.x;
    int tok0 = blockIdx.x * 32;
    for (int i = tid; i < 4096; i += 128) zn_s[i] = g_zn[tok0 * 128 + i];
    __syncthreads();
    {
        float acc[32];
#pragma unroll
        for (int t = 0; t < 32; t++) acc[t] = 0.0f;
        for (int c4 = 0; c4 < 32; c4++) {
            int c = c4 * 4;
            float w0 = W1[(c + 0) * 128 + tid], w1 = W1[(c + 1) * 128 + tid];
            float w2 = W1[(c + 2) * 128 + tid], w3 = W1[(c + 3) * 128 + tid];
#pragma unroll
            for (int t = 0; t < 32; t++) {
                float4 v = ((const float4*)zn_s)[t * 32 + c4];
                acc[t] += v.x * w0 + v.y * w1 + v.z * w2 + v.w * w3;
            }
        }
        float bb = b1[tid];
#pragma unroll
        for (int t = 0; t < 32; t++) mid_s[t * 128 + tid] = gelu_exact(acc[t] + bb);
    }
    __syncthreads();
    {
        float acc[32];
#pragma unroll
        for (int t = 0; t < 32; t++) acc[t] = 0.0f;
        for (int m4 = 0; m4 < 32; m4++) {
            int m = m4 * 4;
            float w0 = W2[(m + 0) * 128 + tid], w1 = W2[(m + 1) * 128 + tid];
            float w2 = W2[(m + 2) * 128 + tid], w3 = W2[(m + 3) * 128 + tid];
#pragma unroll
            for (int t = 0; t < 32; t++) {
                float4 v = ((const float4*)mid_s)[t * 32 + m4];
                acc[t] += v.x * w0 + v.y * w1 + v.z * w2 + v.w * w3;
            }
        }
        float bb = b2[tid];
#pragma unroll
        for (int t = 0; t < 32; t++) g_z[(tok0 + t) * 128 + tid] += acc[t] + bb;
    }
}

// ---------------- final LN + head ----------------
__global__ void __launch_bounds__(256) k_final(
    const float* __restrict__ g, const float* __restrict__ b,
    const float* __restrict__ ow, const float* __restrict__ ob,
    float* __restrict__ out)
{
    int warp = threadIdx.x >> 5, lane = threadIdx.x & 31;
    int n = blockIdx.x * 8 + warp;
    float4 v = ((const float4*)g_z)[n * 32 + lane];
    float s = warp_sum(v.x + v.y + v.z + v.w);
    float mu = s * (1.0f / 128.0f);
    float q = warp_sum(v.x * v.x + v.y * v.y + v.z * v.z + v.w * v.w);
    float var = q * (1.0f / 128.0f) - mu * mu;
    float inv = rsqrtf(var + 1e-5f);
    float4 gg = ((const float4*)g)[lane];
    float4 bb = ((const float4*)b)[lane];
    float4 w4 = ((const float4*)ow)[lane];
    float y0 = (v.x - mu) * inv * gg.x + bb.x;
    float y1 = (v.y - mu) * inv * gg.y + bb.y;
    float y2 = (v.z - mu) * inv * gg.z + bb.z;
    float y3 = (v.w - mu) * inv * gg.w + bb.w;
    float p = warp_sum(y0 * w4.x + y1 * w4.y + y2 * w4.z + y3 * w4.w);
    if (lane == 0) out[n] = p + ob[0];
}

// ---------------- host launch ----------------
extern "C" void kernel_launch(void* const* d_in, const int* in_sizes, int n_in,
                              void* d_out, int out_size)
{
    const float* x        = (const float*)d_in[0];
    const float* fx       = (const float*)d_in[1];
    const float* pre_w1   = (const float*)d_in[2];
    const float* pre_b1   = (const float*)d_in[3];
    const float* pre_w2   = (const float*)d_in[4];
    const float* pre_b2   = (const float*)d_in[5];
    const float* place    = (const float*)d_in[6];
    const float* ln1_g    = (const float*)d_in[7];
    const float* ln1_b    = (const float*)d_in[8];
    const float* convx_w  = (const float*)d_in[9];
    const float* convx_b  = (const float*)d_in[10];
    const float* convfx_w = (const float*)d_in[11];
    const float* convfx_b = (const float*)d_in[12];
    const float* slice_w  = (const float*)d_in[13];
    const float* slice_b  = (const float*)d_in[14];
    const float* temp     = (const float*)d_in[15];
    const float* wq       = (const float*)d_in[16];
    const float* wk       = (const float*)d_in[17];
    const float* wv       = (const float*)d_in[18];
    const float* wo       = (const float*)d_in[19];
    const float* bo       = (const float*)d_in[20];
    const float* ln2_g    = (const float*)d_in[21];
    const float* ln2_b    = (const float*)d_in[22];
    const float* mlp_w1   = (const float*)d_in[23];
    const float* mlp_b1   = (const float*)d_in[24];
    const float* mlp_w2   = (const float*)d_in[25];
    const float* mlp_b2   = (const float*)d_in[26];
    const float* ln3_g    = (const float*)d_in[27];
    const float* ln3_b    = (const float*)d_in[28];
    const float* out_w    = (const float*)d_in[29];
    const float* out_b    = (const float*)d_in[30];
    float* out = (float*)d_out;

    cudaFuncSetAttribute(k_conv_mma,
                         cudaFuncAttributeMaxDynamicSharedMemorySize, CONV_SMEM);

    k_cvt_frag<<<864, 256>>>(convx_w, convfx_w);
    k_pre<<<NTOK / 32, 128>>>(x, fx, pre_w1, pre_b1, pre_w2, pre_b2, place);

    for (int l = 0; l < 2; l++) {
        k_ln<<<NTOK / 8, 256>>>(ln1_g + l * 128, ln1_b + l * 128);
        k_conv_mma<<<dim3(8, 32, 2), 256, CONV_SMEM>>>(
            convx_b + l * 128, convfx_b + l * 128, l);
        k_zero<<<1, 256>>>();
        k_slice<<<128, 256>>>(slice_w + l * 512, slice_b + l * 32, temp + l * 8);
        k_attn<<<1, 256>>>(wq + l * 256, wk + l * 256, wv + l * 256);
        k_deslice<<<NTOK / 16, 128>>>(wo + l * 16384, bo + l * 128);
        k_ln<<<NTOK / 8, 256>>>(ln2_g + l * 128, ln2_b + l * 128);
        k_mlp<<<NTOK / 32, 128>>>(mlp_w1 + l * 16384, mlp_b1 + l * 128,
                                  mlp_w2 + l * 16384, mlp_b2 + l * 128);
    }
    k_final<<<NTOK / 8, 256>>>(ln3_g, ln3_b, out_w, out_b, out);
}

// round 15
// speedup vs baseline: 4.0278x; 1.2249x over previous
#include <cuda_runtime.h>
#include <cuda_fp16.h>
#include <math.h>
#include <stdint.h>

#define NTOK 32768
#define C 128
#define XP 40   // fp16 pitch for ic dimension (conflict-free ldmatrix)

// ---------------- device scratch (no allocations allowed) ----------------
__device__ float g_z[NTOK * C];      // residual stream
__device__ float g_zn[NTOK * C];     // LN output (fp32)
__device__ float g_xmid[NTOK * C];   // conv-x output
__device__ float g_fxmid[NTOK * C];  // conv-fx output
__device__ float g_swt[NTOK * 256];  // slice weights [n][h][g]
__device__ float g_norm[256];        // [h][g]
__device__ float g_toknum[4096];     // [h][g][dh]
__device__ float g_ot[4096];         // [h][g][dh]
__device__ __half g_znh[NTOK * C];   // LN output (fp16, conv A operand)
// conv weights in mma B-fragment order (fp16 hi/lo split):
// [sel][tap][kc(8 = 128ic/16)][npg(8)][lane(32)] -> uint4 = regs (m0,m1,m2,m3)
__device__ uint4 g_wfh[4 * 27 * 8 * 8 * 32];
__device__ uint4 g_wfl[4 * 27 * 8 * 8 * 32];

__device__ __forceinline__ float gelu_exact(float v) {
    return 0.5f * v * (1.0f + erff(v * 0.70710678118654752f));
}

__device__ __forceinline__ float warp_sum(float s) {
#pragma unroll
    for (int o = 16; o; o >>= 1) s += __shfl_xor_sync(0xffffffffu, s, o);
    return s;
}
__device__ __forceinline__ float warp_max(float s) {
#pragma unroll
    for (int o = 16; o; o >>= 1) s = fmaxf(s, __shfl_xor_sync(0xffffffffu, s, o));
    return s;
}

__device__ __forceinline__ void ldsm4(uint32_t* r, uint32_t addr) {
    asm volatile("ldmatrix.sync.aligned.m8n8.x4.shared.b16 {%0,%1,%2,%3}, [%4];"
        : "=r"(r[0]), "=r"(r[1]), "=r"(r[2]), "=r"(r[3]) : "r"(addr));
}
__device__ __forceinline__ void mma_f16(float* d, const uint32_t* a,
                                        uint32_t b0, uint32_t b1) {
    asm volatile(
        "mma.sync.aligned.m16n8k16.row.col.f32.f16.f16.f32 "
        "{%0,%1,%2,%3}, {%4,%5,%6,%7}, {%8,%9}, {%0,%1,%2,%3};"
        : "+f"(d[0]), "+f"(d[1]), "+f"(d[2]), "+f"(d[3])
        : "r"(a[0]), "r"(a[1]), "r"(a[2]), "r"(a[3]), "r"(b0), "r"(b1));
}

// ---------------- weight conversion: fp32 [oc][ic][tap] -> B-fragment uint4 ----------
// One thread per uint4; 221184 total -> 864 blocks of 256. fp16 hi/lo split.
__global__ void __launch_bounds__(256) k_cvt_frag(
    const float* __restrict__ wx, const float* __restrict__ wf)
{
    int idx = blockIdx.x * 256 + threadIdx.x;   // < 221184
    int lane = idx & 31;
    int npg = (idx >> 5) & 7;
    int kc = (idx >> 8) & 7;
    int rest = idx >> 11;       // sel*27 + tap, 0..107
    int tap = rest % 27;
    int sel = rest / 27;
    const float* src = ((sel & 1) ? wf : wx) + (sel >> 1) * 442368;
    int oc0 = npg * 16 + (lane >> 2);
    int k0 = kc * 16 + 2 * (lane & 3);
    uint32_t h[4], l[4];
#pragma unroll
    for (int m = 0; m < 4; m++) {
        int oc = oc0 + ((m >> 1) << 3);
        int kk = k0 + ((m & 1) << 3);
        float v0 = src[(oc * 128 + kk) * 27 + tap];
        float v1 = src[(oc * 128 + kk + 1) * 27 + tap];
        __half h0 = __float2half_rn(v0), h1 = __float2half_rn(v1);
        float r0 = v0 - __half2float(h0), r1 = v1 - __half2float(h1);
        __half l0 = __float2half_rn(r0), l1 = __float2half_rn(r1);
        h[m] = (uint32_t)__half_as_ushort(h0) |
               ((uint32_t)__half_as_ushort(h1) << 16);
        l[m] = (uint32_t)__half_as_ushort(l0) |
               ((uint32_t)__half_as_ushort(l1) << 16);
    }
    g_wfh[idx] = make_uint4(h[0], h[1], h[2], h[3]);
    g_wfl[idx] = make_uint4(l[0], l[1], l[2], l[3]);
}

// ---------------- pre-MLP: z = gelu(h@W1+b1)@W2+b2+placeholder ----------------
__global__ void __launch_bounds__(128) k_pre(
    const float* __restrict__ x, const float* __restrict__ fx,
    const float* __restrict__ W1, const float* __restrict__ b1,
    const float* __restrict__ W2, const float* __restrict__ b2,
    const float* __restrict__ ph)
{
    __shared__ float h_s[32 * 4];
    __shared__ float mid_s[32 * 256];
    int tid = threadIdx.x;
    int tok0 = blockIdx.x * 32;

    for (int i = tid; i < 128; i += 128) {
        int t = i >> 2, j = i & 3;
        h_s[i] = (j < 3) ? x[(tok0 + t) * 3 + j] : fx[tok0 + t];
    }
    __syncthreads();

#pragma unroll
    for (int rep = 0; rep < 2; rep++) {
        int m = tid + rep * 128;
        float w0 = W1[0 * 256 + m], w1 = W1[1 * 256 + m];
        float w2 = W1[2 * 256 + m], w3 = W1[3 * 256 + m];
        float bb = b1[m];
#pragma unroll
        for (int t = 0; t < 32; t++) {
            float4 hv = ((const float4*)h_s)[t];
            float v = bb + hv.x * w0 + hv.y * w1 + hv.z * w2 + hv.w * w3;
            mid_s[t * 256 + m] = gelu_exact(v);
        }
    }
    __syncthreads();

    int o = tid;
    float acc[32];
#pragma unroll
    for (int t = 0; t < 32; t++) acc[t] = 0.0f;
    for (int m4 = 0; m4 < 64; m4++) {
        int m = m4 * 4;
        float w0 = W2[(m + 0) * 128 + o], w1 = W2[(m + 1) * 128 + o];
        float w2 = W2[(m + 2) * 128 + o], w3 = W2[(m + 3) * 128 + o];
#pragma unroll
        for (int t = 0; t < 32; t++) {
            float4 v = ((const float4*)mid_s)[t * 64 + m4];
            acc[t] += v.x * w0 + v.y * w1 + v.z * w2 + v.w * w3;
        }
    }
    float bb = b2[o] + ph[o];
#pragma unroll
    for (int t = 0; t < 32; t++) g_z[(tok0 + t) * 128 + o] = acc[t] + bb;
}

// ---------------- LayerNorm: zn = LN(z)*g+b (fp32 + fp16); optional acc zeroing ----
__global__ void __launch_bounds__(256) k_ln(
    const float* __restrict__ g, const float* __restrict__ b, int dozero)
{
    if (dozero && blockIdx.x == 0) {
        int t = threadIdx.x;
        g_norm[t] = 0.0f;
        for (int i = t; i < 4096; i += 256) g_toknum[i] = 0.0f;
    }
    int warp = threadIdx.x >> 5, lane = threadIdx.x & 31;
    int n = blockIdx.x * 8 + warp;
    float4 v = ((const float4*)g_z)[n * 32 + lane];
    float s = warp_sum(v.x + v.y + v.z + v.w);
    float mu = s * (1.0f / 128.0f);
    float q = warp_sum(v.x * v.x + v.y * v.y + v.z * v.z + v.w * v.w);
    float var = q * (1.0f / 128.0f) - mu * mu;
    float inv = rsqrtf(var + 1e-5f);
    float4 gg = ((const float4*)g)[lane];
    float4 bb = ((const float4*)b)[lane];
    float4 y;
    y.x = (v.x - mu) * inv * gg.x + bb.x;
    y.y = (v.y - mu) * inv * gg.y + bb.y;
    y.z = (v.z - mu) * inv * gg.z + bb.z;
    y.w = (v.w - mu) * inv * gg.w + bb.w;
    ((float4*)g_zn)[n * 32 + lane] = y;
    // fp16 for the tensor-core conv (single precision A operand)
    __half2 p0 = __floats2half2_rn(y.x, y.y);
    __half2 p1 = __floats2half2_rn(y.z, y.w);
    ((__half2*)g_znh)[n * 64 + lane * 2 + 0] = p0;
    ((__half2*)g_znh)[n * 64 + lane * 2 + 1] = p1;
}

// ---------------- conv3d 3x3x3 via fp16 tensor cores (fragment-LDG B) --------------
// grid (8 j-tiles, 32 i, 2 conv). Block 256 thr = 8 warps, 2 CTAs/SM.
// Block tile: 128 tokens (fixed i, 4 j, 32 k) x 128 oc.
// Warp tile: 32 tokens (one j line) x 64 oc. B fragments loaded directly from
// gmem (pre-swizzled, L1/L2 resident).
// 2 mma terms: Ah*Bh + Ah*Bl  (A single fp16, err ~2^-12; B split fp16).
#define CONV_SMEM (612 * XP * 2 + 512)
__global__ void __launch_bounds__(256, 2) k_conv_mma(
    const float* __restrict__ bx, const float* __restrict__ bf, int layer)
{
    extern __shared__ char sm_raw[];
    float* bias_s = (float*)(sm_raw + 612 * XP * 2);

    const int tid = threadIdx.x, lane = tid & 31, warp = tid >> 5;
    const int z = blockIdx.z;
    const int sel = layer * 2 + z;
    const float* bias = z ? bf : bx;
    float* out = z ? g_fxmid : g_xmid;
    const int tg = warp >> 1;   // j-line 0..3 (32 tokens)
    const int og = warp & 1;    // oc half: og*64

    uint32_t su = (uint32_t)__cvta_generic_to_shared(sm_raw);
    const uint32_t xs_u = su;

    if (tid < 128) bias_s[tid] = bias[tid];

    const uint4* __restrict__ wfh = g_wfh + sel * 55296;
    const uint4* __restrict__ wfl = g_wfl + sel * 55296;

    float acc[16][4];   // [mg*8 + np*2 + h][reg]
#pragma unroll
    for (int n = 0; n < 16; n++) {
        acc[n][0] = acc[n][1] = acc[n][2] = acc[n][3] = 0.f;
    }

    const int r15 = lane & 15;
    const int csel = (lane >> 4) * 16;

    for (int cb = 0; cb < 4; cb++) {
        __syncthreads();
        // stage halo neighborhood (3x6x34 positions x 32 ic) fp16
        for (int idx = tid; idx < 2448; idx += 256) {
            int pos = idx >> 2, q = idx & 3;
            int ii = pos / 204; int rem = pos - ii * 204;
            int jj = rem / 34;  int kk = rem - jj * 34;
            int gi = (int)blockIdx.y + ii - 1;
            int gj = (int)blockIdx.x * 4 + jj - 1;
            int gk = kk - 1;
            uint4 v = make_uint4(0u, 0u, 0u, 0u);
            if ((unsigned)gi < 32u && (unsigned)gj < 32u && (unsigned)gk < 32u) {
                int tokn = (gi << 10) + (gj << 5) + gk;
                v = ((const uint4*)g_znh)[tokn * 16 + cb * 4 + q];
            }
            char* dst = sm_raw + pos * (XP * 2) + q * 16;
            *(uint4*)dst = v;
        }
        __syncthreads();

#pragma unroll 1
        for (int t = 0; t < 27; t++) {
            int a = t / 9; int rem9 = t - a * 9;
            int bj = rem9 / 3; int cc = rem9 - bj * 3;
            int lineoff = (a * 6 + tg + bj) * 34;
#pragma unroll
            for (int ks = 0; ks < 2; ks++) {
                int kci = cb * 2 + ks;   // 16-wide k slice within the full 128 ic
                uint32_t off0 = (uint32_t)((lineoff + r15 + cc) * (XP * 2))
                                + csel + ks * 32;
                uint32_t off1 = off0 + 16 * (XP * 2);
                uint32_t Ah0[4], Ah1[4];
                ldsm4(Ah0, xs_u + off0);
                ldsm4(Ah1, xs_u + off1);
                const uint4* bh = wfh + ((t * 8 + kci) * 8 + og * 4) * 32 + lane;
                const uint4* bl = wfl + ((t * 8 + kci) * 8 + og * 4) * 32 + lane;
#pragma unroll
                for (int np = 0; np < 4; np++) {
                    uint4 Bh = bh[np * 32];
                    uint4 Bl = bl[np * 32];
                    mma_f16(acc[np * 2 + 0], Ah0, Bh.x, Bh.y);
                    mma_f16(acc[np * 2 + 0], Ah0, Bl.x, Bl.y);
                    mma_f16(acc[np * 2 + 1], Ah0, Bh.z, Bh.w);
                    mma_f16(acc[np * 2 + 1], Ah0, Bl.z, Bl.w);
                    mma_f16(acc[8 + np * 2 + 0], Ah1, Bh.x, Bh.y);
                    mma_f16(acc[8 + np * 2 + 0], Ah1, Bl.x, Bl.y);
                    mma_f16(acc[8 + np * 2 + 1], Ah1, Bh.z, Bh.w);
                    mma_f16(acc[8 + np * 2 + 1], Ah1, Bl.z, Bl.w);
                }
            }
        }
    }

    // epilogue: acc + bias -> out (fp32)
    int gi = blockIdx.y, gj = blockIdx.x * 4 + tg;
    int base_tok = (gi << 10) + (gj << 5);
#pragma unroll
    for (int mg = 0; mg < 2; mg++) {
#pragma unroll
        for (int np = 0; np < 4; np++) {
#pragma unroll
            for (int h = 0; h < 2; h++) {
                float* a = acc[mg * 8 + np * 2 + h];
                int col = og * 64 + np * 16 + h * 8 + (lane & 3) * 2;
                int tk = base_tok + mg * 16 + (lane >> 2);
                float b0 = bias_s[col], b1 = bias_s[col + 1];
                *(float2*)&out[tk * 128 + col] = make_float2(a[0] + b0, a[1] + b1);
                *(float2*)&out[(tk + 8) * 128 + col] = make_float2(a[2] + b0, a[3] + b1);
            }
        }
    }
}

// ---------------- slice softmax + N-reductions ----------------
__global__ void __launch_bounds__(256) k_slice(
    const float* __restrict__ sw, const float* __restrict__ sb,
    const float* __restrict__ temp)
{
    __shared__ float sw_s[512];
    __shared__ float sb_s[32];
    __shared__ float xm_s[8 * 128];
    __shared__ float fx_s[8 * 128];
    int tid = threadIdx.x;
    int h = tid >> 5;
    int g = tid & 31;
    for (int i = tid; i < 512; i += 256) sw_s[i] = sw[i];
    if (tid < 32) sb_s[tid] = sb[tid];
    float invt = 1.0f / temp[h];
    float nacc = 0.0f;
    float tacc[16];
#pragma unroll
    for (int d = 0; d < 16; d++) tacc[d] = 0.0f;
    int tok0 = blockIdx.x * 256;

    for (int bt = 0; bt < 32; bt++) {
        __syncthreads();
        int tb = tok0 + bt * 8;
        for (int i = tid; i < 1024; i += 256) {
            int t = i >> 7, c = i & 127;
            xm_s[i] = g_xmid[(tb + t) * 128 + c];
            fx_s[i] = g_fxmid[(tb + t) * 128 + c];
        }
        __syncthreads();
#pragma unroll 1
        for (int t = 0; t < 8; t++) {
            float lg = sb_s[g];
#pragma unroll
            for (int d = 0; d < 16; d++) lg += xm_s[t * 128 + h * 16 + d] * sw_s[d * 32 + g];
            lg *= invt;
            float m = warp_max(lg);
            float e = expf(lg - m);
            float s = warp_sum(e);
            float w = e / s;
            g_swt[(tb + t) * 256 + tid] = w;
            nacc += w;
#pragma unroll
            for (int d = 0; d < 16; d++) tacc[d] += fx_s[t * 128 + h * 16 + d] * w;
        }
    }
    atomicAdd(&g_norm[tid], nacc);
#pragma unroll
    for (int d = 0; d < 16; d++) atomicAdd(&g_toknum[tid * 16 + d], tacc[d]);
}

// ---------------- tiny slice attention (1 block, 256 threads) ----------------
__global__ void __launch_bounds__(256) k_attn(
    const float* __restrict__ wq, const float* __restrict__ wk,
    const float* __restrict__ wv)
{
    __shared__ float k_s[4096];
    __shared__ float v_s[4096];
    int tid = threadIdx.x;
    int h = tid >> 5;
    float tokr[16];
    float nrm = g_norm[tid] + 1e-5f;
#pragma unroll
    for (int d = 0; d < 16; d++) tokr[d] = g_toknum[tid * 16 + d] / nrm;
    float q[16];
#pragma unroll
    for (int dd = 0; dd < 16; dd++) {
        float aq = 0.f, ak = 0.f, av = 0.f;
#pragma unroll
        for (int d = 0; d < 16; d++) {
            aq += tokr[d] * wq[d * 16 + dd];
            ak += tokr[d] * wk[d * 16 + dd];
            av += tokr[d] * wv[d * 16 + dd];
        }
        q[dd] = aq;
        k_s[tid * 16 + dd] = ak;
        v_s[tid * 16 + dd] = av;
    }
    __syncthreads();
    float p[32];
    float mx = -1e30f;
#pragma unroll 1
    for (int g2 = 0; g2 < 32; g2++) {
        float s = 0.f;
#pragma unroll
        for (int d = 0; d < 16; d++) s += q[d] * k_s[(h * 32 + g2) * 16 + d];
        s *= 0.25f;
        p[g2] = s;
        mx = fmaxf(mx, s);
    }
    float sum = 0.f;
#pragma unroll
    for (int g2 = 0; g2 < 32; g2++) { p[g2] = expf(p[g2] - mx); sum += p[g2]; }
    float inv = 1.0f / sum;
#pragma unroll 1
    for (int c = 0; c < 16; c++) {
        float o = 0.f;
#pragma unroll
        for (int g2 = 0; g2 < 32; g2++) o += p[g2] * v_s[(h * 32 + g2) * 16 + c];
        g_ot[tid * 16 + c] = o * inv;
    }
}

// ---------------- de-slice + wo projection + residual ----------------
__global__ void __launch_bounds__(128) k_deslice(
    const float* __restrict__ wo, const float* __restrict__ bo)
{
    __shared__ float swt_s[16 * 256];
    __shared__ float tmp_s[16 * 128];
    int tid = threadIdx.x;
    int tok0 = blockIdx.x * 16;
    for (int i = tid; i < 4096; i += 128) swt_s[i] = g_swt[tok0 * 256 + i];
    __syncthreads();
    {
        int c = tid, h = c >> 4, cc = c & 15;
        float acc[16];
#pragma unroll
        for (int t = 0; t < 16; t++) acc[t] = 0.0f;
        for (int g = 0; g < 32; g++) {
            float ov = g_ot[(h * 32 + g) * 16 + cc];
#pragma unroll
            for (int t = 0; t < 16; t++) acc[t] += swt_s[t * 256 + h * 32 + g] * ov;
        }
#pragma unroll
        for (int t = 0; t < 16; t++) tmp_s[t * 128 + c] = acc[t];
    }
    __syncthreads();
    {
        int o = tid;
        float facc[16];
#pragma unroll
        for (int t = 0; t < 16; t++) facc[t] = 0.0f;
        for (int m4 = 0; m4 < 32; m4++) {
            int m = m4 * 4;
            float w0 = wo[(m + 0) * 128 + o], w1 = wo[(m + 1) * 128 + o];
            float w2 = wo[(m + 2) * 128 + o], w3 = wo[(m + 3) * 128 + o];
#pragma unroll
            for (int t = 0; t < 16; t++) {
                float4 v = ((const float4*)tmp_s)[t * 32 + m4];
                facc[t] += v.x * w0 + v.y * w1 + v.z * w2 + v.w * w3;
            }
        }
        float bv = bo[o];
#pragma unroll
        for (int t = 0; t < 16; t++) g_z[(tok0 + t) * 128 + o] += facc[t] + bv;
    }
}

// ---------------- MLP: z += gelu(zn@W1+b1)@W2+b2 ----------------
__global__ void __launch_bounds__(128) k_mlp(
    const float* __restrict__ W1, const float* __restrict__ b1,
    const float* __restrict__ W2, const float* __restrict__ b2)
{
    __shared__ float zn_s[32 * 128];
    __shared__ float mid_s[32 * 128];
    int tid = threadIdx.x;
    int tok0 = blockIdx.x * 32;
    for (int i = tid; i < 4096; i += 128) zn_s[i] = g_zn[tok0 * 128 + i];
    __syncthreads();
    {
        float acc[32];
#pragma unroll
        for (int t = 0; t < 32; t++) acc[t] = 0.0f;
        for (int c4 = 0; c4 < 32; c4++) {
            int c = c4 * 4;
            float w0 = W1[(c + 0) * 128 + tid], w1 = W1[(c + 1) * 128 + tid];
            float w2 = W1[(c + 2) * 128 + tid], w3 = W1[(c + 3) * 128 + tid];
#pragma unroll
            for (int t = 0; t < 32; t++) {
                float4 v = ((const float4*)zn_s)[t * 32 + c4];
                acc[t] += v.x * w0 + v.y * w1 + v.z * w2 + v.w * w3;
            }
        }
        float bb = b1[tid];
#pragma unroll
        for (int t = 0; t < 32; t++) mid_s[t * 128 + tid] = gelu_exact(acc[t] + bb);
    }
    __syncthreads();
    {
        float acc[32];
#pragma unroll
        for (int t = 0; t < 32; t++) acc[t] = 0.0f;
        for (int m4 = 0; m4 < 32; m4++) {
            int m = m4 * 4;
            float w0 = W2[(m + 0) * 128 + tid], w1 = W2[(m + 1) * 128 + tid];
            float w2 = W2[(m + 2) * 128 + tid], w3 = W2[(m + 3) * 128 + tid];
#pragma unroll
            for (int t = 0; t < 32; t++) {
                float4 v = ((const float4*)mid_s)[t * 32 + m4];
                acc[t] += v.x * w0 + v.y * w1 + v.z * w2 + v.w * w3;
            }
        }
        float bb = b2[tid];
#pragma unroll
        for (int t = 0; t < 32; t++) g_z[(tok0 + t) * 128 + tid] += acc[t] + bb;
    }
}

// ---------------- final LN + head ----------------
__global__ void __launch_bounds__(256) k_final(
    const float* __restrict__ g, const float* __restrict__ b,
    const float* __restrict__ ow, const float* __restrict__ ob,
    float* __restrict__ out)
{
    int warp = threadIdx.x >> 5, lane = threadIdx.x & 31;
    int n = blockIdx.x * 8 + warp;
    float4 v = ((const float4*)g_z)[n * 32 + lane];
    float s = warp_sum(v.x + v.y + v.z + v.w);
    float mu = s * (1.0f / 128.0f);
    float q = warp_sum(v.x * v.x + v.y * v.y + v.z * v.z + v.w * v.w);
    float var = q * (1.0f / 128.0f) - mu * mu;
    float inv = rsqrtf(var + 1e-5f);
    float4 gg = ((const float4*)g)[lane];
    float4 bb = ((const float4*)b)[lane];
    float4 w4 = ((const float4*)ow)[lane];
    float y0 = (v.x - mu) * inv * gg.x + bb.x;
    float y1 = (v.y - mu) * inv * gg.y + bb.y;
    float y2 = (v.z - mu) * inv * gg.z + bb.z;
    float y3 = (v.w - mu) * inv * gg.w + bb.w;
    float p = warp_sum(y0 * w4.x + y1 * w4.y + y2 * w4.z + y3 * w4.w);
    if (lane == 0) out[n] = p + ob[0];
}

// ---------------- host launch ----------------
extern "C" void kernel_launch(void* const* d_in, const int* in_sizes, int n_in,
                              void* d_out, int out_size)
{
    const float* x        = (const float*)d_in[0];
    const float* fx       = (const float*)d_in[1];
    const float* pre_w1   = (const float*)d_in[2];
    const float* pre_b1   = (const float*)d_in[3];
    const float* pre_w2   = (const float*)d_in[4];
    const float* pre_b2   = (const float*)d_in[5];
    const float* place    = (const float*)d_in[6];
    const float* ln1_g    = (const float*)d_in[7];
    const float* ln1_b    = (const float*)d_in[8];
    const float* convx_w  = (const float*)d_in[9];
    const float* convx_b  = (const float*)d_in[10];
    const float* convfx_w = (const float*)d_in[11];
    const float* convfx_b = (const float*)d_in[12];
    const float* slice_w  = (const float*)d_in[13];
    const float* slice_b  = (const float*)d_in[14];
    const float* temp     = (const float*)d_in[15];
    const float* wq       = (const float*)d_in[16];
    const float* wk       = (const float*)d_in[17];
    const float* wv       = (const float*)d_in[18];
    const float* wo       = (const float*)d_in[19];
    const float* bo       = (const float*)d_in[20];
    const float* ln2_g    = (const float*)d_in[21];
    const float* ln2_b    = (const float*)d_in[22];
    const float* mlp_w1   = (const float*)d_in[23];
    const float* mlp_b1   = (const float*)d_in[24];
    const float* mlp_w2   = (const float*)d_in[25];
    const float* mlp_b2   = (const float*)d_in[26];
    const float* ln3_g    = (const float*)d_in[27];
    const float* ln3_b    = (const float*)d_in[28];
    const float* out_w    = (const float*)d_in[29];
    const float* out_b    = (const float*)d_in[30];
    float* out = (float*)d_out;

    cudaFuncSetAttribute(k_conv_mma,
                         cudaFuncAttributeMaxDynamicSharedMemorySize, CONV_SMEM);

    k_cvt_frag<<<864, 256>>>(convx_w, convfx_w);
    k_pre<<<NTOK / 32, 128>>>(x, fx, pre_w1, pre_b1, pre_w2, pre_b2, place);

    for (int l = 0; l < 2; l++) {
        k_ln<<<NTOK / 8, 256>>>(ln1_g + l * 128, ln1_b + l * 128, 1);
        k_conv_mma<<<dim3(8, 32, 2), 256, CONV_SMEM>>>(
            convx_b + l * 128, convfx_b + l * 128, l);
        k_slice<<<128, 256>>>(slice_w + l * 512, slice_b + l * 32, temp + l * 8);
        k_attn<<<1, 256>>>(wq + l * 256, wk + l * 256, wv + l * 256);
        k_deslice<<<NTOK / 16, 128>>>(wo + l * 16384, bo + l * 128);
        k_ln<<<NTOK / 8, 256>>>(ln2_g + l * 128, ln2_b + l * 128, 0);
        k_mlp<<<NTOK / 32, 128>>>(mlp_w1 + l * 16384, mlp_b1 + l * 128,
                                  mlp_w2 + l * 16384, mlp_b2 + l * 128);
    }
    k_final<<<NTOK / 8, 256>>>(ln3_g, ln3_b, out_w, out_b, out);
}

// round 16
// speedup vs baseline: 4.5555x; 1.1310x over previous
#include <cuda_runtime.h>
#include <cuda_fp16.h>
#include <math.h>
#include <stdint.h>

#define NTOK 32768
#define C 128
#define XP 40   // fp16 pitch for ic dimension (conflict-free ldmatrix)

// ---------------- device scratch (no allocations allowed) ----------------
__device__ float g_z[NTOK * C];      // residual stream
__device__ float g_xmid[NTOK * C];   // conv-x output
__device__ float g_fxmid[NTOK * C];  // conv-fx output
__device__ float g_swt[NTOK * 256];  // slice weights [n][h][g]
__device__ float g_norm[256];        // [h][g]
__device__ float g_toknum[4096];     // [h][g][dh]
__device__ float g_ot[4096];         // [h][g][dh]
__device__ __half g_znh[NTOK * C];   // LN output (fp16, mma A operand)
// conv weights in mma B-fragment order (fp16 hi/lo split):
// [sel][tap][kc(8)][npg(8)][lane(32)] -> uint4 = regs (m0,m1,m2,m3)
__device__ uint4 g_wfh[4 * 27 * 8 * 8 * 32];
__device__ uint4 g_wfl[4 * 27 * 8 * 8 * 32];
// mlp weights in mma B-fragment order: [layer][mat][kc(8)][npg(8)][lane(32)]
__device__ uint4 g_mwh[2 * 2 * 8 * 8 * 32];
__device__ uint4 g_mwl[2 * 2 * 8 * 8 * 32];

__device__ __forceinline__ float gelu_exact(float v) {
    return 0.5f * v * (1.0f + erff(v * 0.70710678118654752f));
}

__device__ __forceinline__ float warp_sum(float s) {
#pragma unroll
    for (int o = 16; o; o >>= 1) s += __shfl_xor_sync(0xffffffffu, s, o);
    return s;
}
__device__ __forceinline__ float warp_max(float s) {
#pragma unroll
    for (int o = 16; o; o >>= 1) s = fmaxf(s, __shfl_xor_sync(0xffffffffu, s, o));
    return s;
}

__device__ __forceinline__ void ldsm4(uint32_t* r, uint32_t addr) {
    asm volatile("ldmatrix.sync.aligned.m8n8.x4.shared.b16 {%0,%1,%2,%3}, [%4];"
        : "=r"(r[0]), "=r"(r[1]), "=r"(r[2]), "=r"(r[3]) : "r"(addr));
}
__device__ __forceinline__ void mma_f16(float* d, const uint32_t* a,
                                        uint32_t b0, uint32_t b1) {
    asm volatile(
        "mma.sync.aligned.m16n8k16.row.col.f32.f16.f16.f32 "
        "{%0,%1,%2,%3}, {%4,%5,%6,%7}, {%8,%9}, {%0,%1,%2,%3};"
        : "+f"(d[0]), "+f"(d[1]), "+f"(d[2]), "+f"(d[3])
        : "r"(a[0]), "r"(a[1]), "r"(a[2]), "r"(a[3]), "r"(b0), "r"(b1));
}

__device__ __forceinline__ void split_pack(float v0, float v1,
                                           uint32_t& hh, uint32_t& ll) {
    __half h0 = __float2half_rn(v0), h1 = __float2half_rn(v1);
    float r0 = v0 - __half2float(h0), r1 = v1 - __half2float(h1);
    __half l0 = __float2half_rn(r0), l1 = __float2half_rn(r1);
    hh = (uint32_t)__half_as_ushort(h0) | ((uint32_t)__half_as_ushort(h1) << 16);
    ll = (uint32_t)__half_as_ushort(l0) | ((uint32_t)__half_as_ushort(l1) << 16);
}

// ---------------- conv weight conversion: fp32 [oc][ic][tap] -> B-fragment uint4 ----
__global__ void __launch_bounds__(256) k_cvt_frag(
    const float* __restrict__ wx, const float* __restrict__ wf)
{
    int idx = blockIdx.x * 256 + threadIdx.x;   // < 221184
    int lane = idx & 31;
    int npg = (idx >> 5) & 7;
    int kc = (idx >> 8) & 7;
    int rest = idx >> 11;       // sel*27 + tap, 0..107
    int tap = rest % 27;
    int sel = rest / 27;
    const float* src = ((sel & 1) ? wf : wx) + (sel >> 1) * 442368;
    int oc0 = npg * 16 + (lane >> 2);
    int k0 = kc * 16 + 2 * (lane & 3);
    uint32_t h[4], l[4];
#pragma unroll
    for (int m = 0; m < 4; m++) {
        int oc = oc0 + ((m >> 1) << 3);
        int kk = k0 + ((m & 1) << 3);
        split_pack(src[(oc * 128 + kk) * 27 + tap],
                   src[(oc * 128 + kk + 1) * 27 + tap], h[m], l[m]);
    }
    g_wfh[idx] = make_uint4(h[0], h[1], h[2], h[3]);
    g_wfl[idx] = make_uint4(l[0], l[1], l[2], l[3]);
}

// ---------------- mlp weight conversion: fp32 [c_in][c_out] -> B-fragment uint4 -----
// B[n][k] = W[k][n] (k = c_in, n = c_out).
__global__ void __launch_bounds__(256) k_cvt_mlp(
    const float* __restrict__ w1, const float* __restrict__ w2)
{
    int idx = blockIdx.x * 256 + threadIdx.x;   // < 8192
    int lane = idx & 31;
    int npg = (idx >> 5) & 7;
    int kc = (idx >> 8) & 7;
    int rest = idx >> 11;       // layer*2 + mat
    const float* src = ((rest & 1) ? w2 : w1) + (rest >> 1) * 16384;
    int oc0 = npg * 16 + (lane >> 2);
    int k0 = kc * 16 + 2 * (lane & 3);
    uint32_t h[4], l[4];
#pragma unroll
    for (int m = 0; m < 4; m++) {
        int oc = oc0 + ((m >> 1) << 3);
        int kk = k0 + ((m & 1) << 3);
        split_pack(src[kk * 128 + oc], src[(kk + 1) * 128 + oc], h[m], l[m]);
    }
    g_mwh[idx] = make_uint4(h[0], h[1], h[2], h[3]);
    g_mwl[idx] = make_uint4(l[0], l[1], l[2], l[3]);
}

// ---------------- pre-MLP: z = gelu(h@W1+b1)@W2+b2+placeholder ----------------
__global__ void __launch_bounds__(128) k_pre(
    const float* __restrict__ x, const float* __restrict__ fx,
    const float* __restrict__ W1, const float* __restrict__ b1,
    const float* __restrict__ W2, const float* __restrict__ b2,
    const float* __restrict__ ph)
{
    __shared__ float h_s[32 * 4];
    __shared__ float mid_s[32 * 256];
    int tid = threadIdx.x;
    int tok0 = blockIdx.x * 32;

    for (int i = tid; i < 128; i += 128) {
        int t = i >> 2, j = i & 3;
        h_s[i] = (j < 3) ? x[(tok0 + t) * 3 + j] : fx[tok0 + t];
    }
    __syncthreads();

#pragma unroll
    for (int rep = 0; rep < 2; rep++) {
        int m = tid + rep * 128;
        float w0 = W1[0 * 256 + m], w1 = W1[1 * 256 + m];
        float w2 = W1[2 * 256 + m], w3 = W1[3 * 256 + m];
        float bb = b1[m];
#pragma unroll
        for (int t = 0; t < 32; t++) {
            float4 hv = ((const float4*)h_s)[t];
            float v = bb + hv.x * w0 + hv.y * w1 + hv.z * w2 + hv.w * w3;
            mid_s[t * 256 + m] = gelu_exact(v);
        }
    }
    __syncthreads();

    int o = tid;
    float acc[32];
#pragma unroll
    for (int t = 0; t < 32; t++) acc[t] = 0.0f;
    for (int m4 = 0; m4 < 64; m4++) {
        int m = m4 * 4;
        float w0 = W2[(m + 0) * 128 + o], w1 = W2[(m + 1) * 128 + o];
        float w2 = W2[(m + 2) * 128 + o], w3 = W2[(m + 3) * 128 + o];
#pragma unroll
        for (int t = 0; t < 32; t++) {
            float4 v = ((const float4*)mid_s)[t * 64 + m4];
            acc[t] += v.x * w0 + v.y * w1 + v.z * w2 + v.w * w3;
        }
    }
    float bb = b2[o] + ph[o];
#pragma unroll
    for (int t = 0; t < 32; t++) g_z[(tok0 + t) * 128 + o] = acc[t] + bb;
}

// ---------------- LayerNorm: znh = fp16(LN(z)*g+b); optional acc zeroing ----------
__global__ void __launch_bounds__(256) k_ln(
    const float* __restrict__ g, const float* __restrict__ b, int dozero)
{
    if (dozero && blockIdx.x == 0) {
        int t = threadIdx.x;
        g_norm[t] = 0.0f;
        for (int i = t; i < 4096; i += 256) g_toknum[i] = 0.0f;
    }
    int warp = threadIdx.x >> 5, lane = threadIdx.x & 31;
    int n = blockIdx.x * 8 + warp;
    float4 v = ((const float4*)g_z)[n * 32 + lane];
    float s = warp_sum(v.x + v.y + v.z + v.w);
    float mu = s * (1.0f / 128.0f);
    float q = warp_sum(v.x * v.x + v.y * v.y + v.z * v.z + v.w * v.w);
    float var = q * (1.0f / 128.0f) - mu * mu;
    float inv = rsqrtf(var + 1e-5f);
    float4 gg = ((const float4*)g)[lane];
    float4 bb = ((const float4*)b)[lane];
    float y0 = (v.x - mu) * inv * gg.x + bb.x;
    float y1 = (v.y - mu) * inv * gg.y + bb.y;
    float y2 = (v.z - mu) * inv * gg.z + bb.z;
    float y3 = (v.w - mu) * inv * gg.w + bb.w;
    __half2 p0 = __floats2half2_rn(y0, y1);
    __half2 p1 = __floats2half2_rn(y2, y3);
    ((__half2*)g_znh)[n * 64 + lane * 2 + 0] = p0;
    ((__half2*)g_znh)[n * 64 + lane * 2 + 1] = p1;
}

// ---------------- conv3d 3x3x3 via fp16 tensor cores (fragment-LDG B) --------------
#define CONV_SMEM (612 * XP * 2 + 512)
__global__ void __launch_bounds__(256, 2) k_conv_mma(
    const float* __restrict__ bx, const float* __restrict__ bf, int layer)
{
    extern __shared__ char sm_raw[];
    float* bias_s = (float*)(sm_raw + 612 * XP * 2);

    const int tid = threadIdx.x, lane = tid & 31, warp = tid >> 5;
    const int z = blockIdx.z;
    const int sel = layer * 2 + z;
    const float* bias = z ? bf : bx;
    float* out = z ? g_fxmid : g_xmid;
    const int tg = warp >> 1;   // j-line 0..3 (32 tokens)
    const int og = warp & 1;    // oc half: og*64

    uint32_t su = (uint32_t)__cvta_generic_to_shared(sm_raw);
    const uint32_t xs_u = su;

    if (tid < 128) bias_s[tid] = bias[tid];

    const uint4* __restrict__ wfh = g_wfh + sel * 55296;
    const uint4* __restrict__ wfl = g_wfl + sel * 55296;

    float acc[16][4];
#pragma unroll
    for (int n = 0; n < 16; n++) {
        acc[n][0] = acc[n][1] = acc[n][2] = acc[n][3] = 0.f;
    }

    const int r15 = lane & 15;
    const int csel = (lane >> 4) * 16;

    for (int cb = 0; cb < 4; cb++) {
        __syncthreads();
        for (int idx = tid; idx < 2448; idx += 256) {
            int pos = idx >> 2, q = idx & 3;
            int ii = pos / 204; int rem = pos - ii * 204;
            int jj = rem / 34;  int kk = rem - jj * 34;
            int gi = (int)blockIdx.y + ii - 1;
            int gj = (int)blockIdx.x * 4 + jj - 1;
            int gk = kk - 1;
            uint4 v = make_uint4(0u, 0u, 0u, 0u);
            if ((unsigned)gi < 32u && (unsigned)gj < 32u && (unsigned)gk < 32u) {
                int tokn = (gi << 10) + (gj << 5) + gk;
                v = ((const uint4*)g_znh)[tokn * 16 + cb * 4 + q];
            }
            char* dst = sm_raw + pos * (XP * 2) + q * 16;
            *(uint4*)dst = v;
        }
        __syncthreads();

#pragma unroll 1
        for (int t = 0; t < 27; t++) {
            int a = t / 9; int rem9 = t - a * 9;
            int bj = rem9 / 3; int cc = rem9 - bj * 3;
            int lineoff = (a * 6 + tg + bj) * 34;
#pragma unroll
            for (int ks = 0; ks < 2; ks++) {
                int kci = cb * 2 + ks;
                uint32_t off0 = (uint32_t)((lineoff + r15 + cc) * (XP * 2))
                                + csel + ks * 32;
                uint32_t off1 = off0 + 16 * (XP * 2);
                uint32_t Ah0[4], Ah1[4];
                ldsm4(Ah0, xs_u + off0);
                ldsm4(Ah1, xs_u + off1);
                const uint4* bh = wfh + ((t * 8 + kci) * 8 + og * 4) * 32 + lane;
                const uint4* bl = wfl + ((t * 8 + kci) * 8 + og * 4) * 32 + lane;
#pragma unroll
                for (int np = 0; np < 4; np++) {
                    uint4 Bh = bh[np * 32];
                    uint4 Bl = bl[np * 32];
                    mma_f16(acc[np * 2 + 0], Ah0, Bh.x, Bh.y);
                    mma_f16(acc[np * 2 + 0], Ah0, Bl.x, Bl.y);
                    mma_f16(acc[np * 2 + 1], Ah0, Bh.z, Bh.w);
                    mma_f16(acc[np * 2 + 1], Ah0, Bl.z, Bl.w);
                    mma_f16(acc[8 + np * 2 + 0], Ah1, Bh.x, Bh.y);
                    mma_f16(acc[8 + np * 2 + 0], Ah1, Bl.x, Bl.y);
                    mma_f16(acc[8 + np * 2 + 1], Ah1, Bh.z, Bh.w);
                    mma_f16(acc[8 + np * 2 + 1], Ah1, Bl.z, Bl.w);
                }
            }
        }
    }

    int gi = blockIdx.y, gj = blockIdx.x * 4 + tg;
    int base_tok = (gi << 10) + (gj << 5);
#pragma unroll
    for (int mg = 0; mg < 2; mg++) {
#pragma unroll
        for (int np = 0; np < 4; np++) {
#pragma unroll
            for (int h = 0; h < 2; h++) {
                float* a = acc[mg * 8 + np * 2 + h];
                int col = og * 64 + np * 16 + h * 8 + (lane & 3) * 2;
                int tk = base_tok + mg * 16 + (lane >> 2);
                float b0 = bias_s[col], b1 = bias_s[col + 1];
                *(float2*)&out[tk * 128 + col] = make_float2(a[0] + b0, a[1] + b1);
                *(float2*)&out[(tk + 8) * 128 + col] = make_float2(a[2] + b0, a[3] + b1);
            }
        }
    }
}

// ---------------- MLP via fp16 tensor cores: z += gelu(znh@W1+b1)@W2+b2 ------------
// grid 256 (128 tokens each), block 256 = 8 warps. Warp: 32 tokens x 64 oc.
// GEMM1 -> bias+gelu fp32 -> fp16 mid tile -> GEMM2 -> bias+residual -> g_z.
#define MLP_PITCH 272   // bytes per row (136 fp16 = 17 x 16B, odd -> conflict-free)
#define MLP_SMEM (2 * 128 * MLP_PITCH + 1024)
__global__ void __launch_bounds__(256, 2) k_mlp_mma(
    const float* __restrict__ b1, const float* __restrict__ b2, int layer)
{
    extern __shared__ char sm_raw[];
    float* bias_s = (float*)(sm_raw + 2 * 128 * MLP_PITCH);
    const int tid = threadIdx.x, lane = tid & 31, warp = tid >> 5;
    const int tg = warp >> 1, og = warp & 1;
    const int tok0 = blockIdx.x * 128;
    uint32_t su = (uint32_t)__cvta_generic_to_shared(sm_raw);
    const uint32_t a_u = su;
    const uint32_t mid_u = su + 128 * MLP_PITCH;

    bias_s[tid] = (tid < 128) ? b1[tid] : b2[tid - 128];

    // stage A (128 tokens x 128 c fp16)
    for (int idx = tid; idx < 2048; idx += 256) {
        int row = idx >> 4, q = idx & 15;
        uint4 v = ((const uint4*)g_znh)[(tok0 + row) * 16 + q];
        *(uint4*)(sm_raw + row * MLP_PITCH + q * 16) = v;
    }
    __syncthreads();

    const int r15 = lane & 15, csel = (lane >> 4) * 16;
    const uint4* wh1 = g_mwh + (layer * 2 + 0) * 2048;
    const uint4* wl1 = g_mwl + (layer * 2 + 0) * 2048;
    const uint4* wh2 = g_mwh + (layer * 2 + 1) * 2048;
    const uint4* wl2 = g_mwl + (layer * 2 + 1) * 2048;

    float acc[16][4];
#pragma unroll
    for (int n = 0; n < 16; n++)
        acc[n][0] = acc[n][1] = acc[n][2] = acc[n][3] = 0.f;

    // GEMM1
#pragma unroll 1
    for (int kc = 0; kc < 8; kc++) {
        uint32_t off0 = (uint32_t)((tg * 32 + r15) * MLP_PITCH) + kc * 32 + csel;
        uint32_t off1 = off0 + 16 * MLP_PITCH;
        uint32_t Ah0[4], Ah1[4];
        ldsm4(Ah0, a_u + off0);
        ldsm4(Ah1, a_u + off1);
        const uint4* bh = wh1 + kc * 256 + og * 128 + lane;
        const uint4* bl = wl1 + kc * 256 + og * 128 + lane;
#pragma unroll
        for (int np = 0; np < 4; np++) {
            uint4 Bh = bh[np * 32];
            uint4 Bl = bl[np * 32];
            mma_f16(acc[np * 2 + 0], Ah0, Bh.x, Bh.y);
            mma_f16(acc[np * 2 + 0], Ah0, Bl.x, Bl.y);
            mma_f16(acc[np * 2 + 1], Ah0, Bh.z, Bh.w);
            mma_f16(acc[np * 2 + 1], Ah0, Bl.z, Bl.w);
            mma_f16(acc[8 + np * 2 + 0], Ah1, Bh.x, Bh.y);
            mma_f16(acc[8 + np * 2 + 0], Ah1, Bl.x, Bl.y);
            mma_f16(acc[8 + np * 2 + 1], Ah1, Bh.z, Bh.w);
            mma_f16(acc[8 + np * 2 + 1], Ah1, Bl.z, Bl.w);
        }
    }

    // epilogue1: bias + gelu -> fp16 mid tile
#pragma unroll
    for (int mg = 0; mg < 2; mg++) {
#pragma unroll
        for (int np = 0; np < 4; np++) {
#pragma unroll
            for (int h = 0; h < 2; h++) {
                float* a = acc[mg * 8 + np * 2 + h];
                int col = og * 64 + np * 16 + h * 8 + (lane & 3) * 2;
                int row = tg * 32 + mg * 16 + (lane >> 2);
                float bb0 = bias_s[col], bb1 = bias_s[col + 1];
                __half2 v0 = __floats2half2_rn(gelu_exact(a[0] + bb0),
                                               gelu_exact(a[1] + bb1));
                __half2 v1 = __floats2half2_rn(gelu_exact(a[2] + bb0),
                                               gelu_exact(a[3] + bb1));
                *(__half2*)(sm_raw + 128 * MLP_PITCH + row * MLP_PITCH + col * 2) = v0;
                *(__half2*)(sm_raw + 128 * MLP_PITCH + (row + 8) * MLP_PITCH + col * 2) = v1;
            }
        }
    }
    __syncthreads();

#pragma unroll
    for (int n = 0; n < 16; n++)
        acc[n][0] = acc[n][1] = acc[n][2] = acc[n][3] = 0.f;

    // GEMM2
#pragma unroll 1
    for (int kc = 0; kc < 8; kc++) {
        uint32_t off0 = (uint32_t)((tg * 32 + r15) * MLP_PITCH) + kc * 32 + csel;
        uint32_t off1 = off0 + 16 * MLP_PITCH;
        uint32_t Ah0[4], Ah1[4];
        ldsm4(Ah0, mid_u + off0);
        ldsm4(Ah1, mid_u + off1);
        const uint4* bh = wh2 + kc * 256 + og * 128 + lane;
        const uint4* bl = wl2 + kc * 256 + og * 128 + lane;
#pragma unroll
        for (int np = 0; np < 4; np++) {
            uint4 Bh = bh[np * 32];
            uint4 Bl = bl[np * 32];
            mma_f16(acc[np * 2 + 0], Ah0, Bh.x, Bh.y);
            mma_f16(acc[np * 2 + 0], Ah0, Bl.x, Bl.y);
            mma_f16(acc[np * 2 + 1], Ah0, Bh.z, Bh.w);
            mma_f16(acc[np * 2 + 1], Ah0, Bl.z, Bl.w);
            mma_f16(acc[8 + np * 2 + 0], Ah1, Bh.x, Bh.y);
            mma_f16(acc[8 + np * 2 + 0], Ah1, Bl.x, Bl.y);
            mma_f16(acc[8 + np * 2 + 1], Ah1, Bh.z, Bh.w);
            mma_f16(acc[8 + np * 2 + 1], Ah1, Bl.z, Bl.w);
        }
    }

    // epilogue2: bias + residual -> g_z
#pragma unroll
    for (int mg = 0; mg < 2; mg++) {
#pragma unroll
        for (int np = 0; np < 4; np++) {
#pragma unroll
            for (int h = 0; h < 2; h++) {
                float* a = acc[mg * 8 + np * 2 + h];
                int col = og * 64 + np * 16 + h * 8 + (lane & 3) * 2;
                int row = tg * 32 + mg * 16 + (lane >> 2);
                float bb0 = bias_s[128 + col], bb1 = bias_s[128 + col + 1];
                float2 r0 = *(float2*)&g_z[(tok0 + row) * 128 + col];
                float2 r1 = *(float2*)&g_z[(tok0 + row + 8) * 128 + col];
                *(float2*)&g_z[(tok0 + row) * 128 + col] =
                    make_float2(a[0] + bb0 + r0.x, a[1] + bb1 + r0.y);
                *(float2*)&g_z[(tok0 + row + 8) * 128 + col] =
                    make_float2(a[2] + bb0 + r1.x, a[3] + bb1 + r1.y);
            }
        }
    }
}

// ---------------- slice softmax + N-reductions ----------------
__global__ void __launch_bounds__(256) k_slice(
    const float* __restrict__ sw, const float* __restrict__ sb,
    const float* __restrict__ temp)
{
    __shared__ float sw_s[512];
    __shared__ float sb_s[32];
    __shared__ float xm_s[8 * 128];
    __shared__ float fx_s[8 * 128];
    int tid = threadIdx.x;
    int h = tid >> 5;
    int g = tid & 31;
    for (int i = tid; i < 512; i += 256) sw_s[i] = sw[i];
    if (tid < 32) sb_s[tid] = sb[tid];
    float invt = 1.0f / temp[h];
    float nacc = 0.0f;
    float tacc[16];
#pragma unroll
    for (int d = 0; d < 16; d++) tacc[d] = 0.0f;
    int tok0 = blockIdx.x * 256;

    for (int bt = 0; bt < 32; bt++) {
        __syncthreads();
        int tb = tok0 + bt * 8;
        for (int i = tid; i < 1024; i += 256) {
            int t = i >> 7, c = i & 127;
            xm_s[i] = g_xmid[(tb + t) * 128 + c];
            fx_s[i] = g_fxmid[(tb + t) * 128 + c];
        }
        __syncthreads();
#pragma unroll 1
        for (int t = 0; t < 8; t++) {
            float lg = sb_s[g];
#pragma unroll
            for (int d = 0; d < 16; d++) lg += xm_s[t * 128 + h * 16 + d] * sw_s[d * 32 + g];
            lg *= invt;
            float m = warp_max(lg);
            float e = expf(lg - m);
            float s = warp_sum(e);
            float w = e / s;
            g_swt[(tb + t) * 256 + tid] = w;
            nacc += w;
#pragma unroll
            for (int d = 0; d < 16; d++) tacc[d] += fx_s[t * 128 + h * 16 + d] * w;
        }
    }
    atomicAdd(&g_norm[tid], nacc);
#pragma unroll
    for (int d = 0; d < 16; d++) atomicAdd(&g_toknum[tid * 16 + d], tacc[d]);
}

// ---------------- tiny slice attention (1 block, 256 threads) ----------------
__global__ void __launch_bounds__(256) k_attn(
    const float* __restrict__ wq, const float* __restrict__ wk,
    const float* __restrict__ wv)
{
    __shared__ float k_s[4096];
    __shared__ float v_s[4096];
    int tid = threadIdx.x;
    int h = tid >> 5;
    float tokr[16];
    float nrm = g_norm[tid] + 1e-5f;
#pragma unroll
    for (int d = 0; d < 16; d++) tokr[d] = g_toknum[tid * 16 + d] / nrm;
    float q[16];
#pragma unroll
    for (int dd = 0; dd < 16; dd++) {
        float aq = 0.f, ak = 0.f, av = 0.f;
#pragma unroll
        for (int d = 0; d < 16; d++) {
            aq += tokr[d] * wq[d * 16 + dd];
            ak += tokr[d] * wk[d * 16 + dd];
            av += tokr[d] * wv[d * 16 + dd];
        }
        q[dd] = aq;
        k_s[tid * 16 + dd] = ak;
        v_s[tid * 16 + dd] = av;
    }
    __syncthreads();
    float p[32];
    float mx = -1e30f;
#pragma unroll 1
    for (int g2 = 0; g2 < 32; g2++) {
        float s = 0.f;
#pragma unroll
        for (int d = 0; d < 16; d++) s += q[d] * k_s[(h * 32 + g2) * 16 + d];
        s *= 0.25f;
        p[g2] = s;
        mx = fmaxf(mx, s);
    }
    float sum = 0.f;
#pragma unroll
    for (int g2 = 0; g2 < 32; g2++) { p[g2] = expf(p[g2] - mx); sum += p[g2]; }
    float inv = 1.0f / sum;
#pragma unroll 1
    for (int c = 0; c < 16; c++) {
        float o = 0.f;
#pragma unroll
        for (int g2 = 0; g2 < 32; g2++) o += p[g2] * v_s[(h * 32 + g2) * 16 + c];
        g_ot[tid * 16 + c] = o * inv;
    }
}

// ---------------- de-slice + wo projection + residual ----------------
__global__ void __launch_bounds__(128) k_deslice(
    const float* __restrict__ wo, const float* __restrict__ bo)
{
    __shared__ float swt_s[16 * 256];
    __shared__ float tmp_s[16 * 128];
    int tid = threadIdx.x;
    int tok0 = blockIdx.x * 16;
    for (int i = tid; i < 4096; i += 128) swt_s[i] = g_swt[tok0 * 256 + i];
    __syncthreads();
    {
        int c = tid, h = c >> 4, cc = c & 15;
        float acc[16];
#pragma unroll
        for (int t = 0; t < 16; t++) acc[t] = 0.0f;
        for (int g = 0; g < 32; g++) {
            float ov = g_ot[(h * 32 + g) * 16 + cc];
#pragma unroll
            for (int t = 0; t < 16; t++) acc[t] += swt_s[t * 256 + h * 32 + g] * ov;
        }
#pragma unroll
        for (int t = 0; t < 16; t++) tmp_s[t * 128 + c] = acc[t];
    }
    __syncthreads();
    {
        int o = tid;
        float facc[16];
#pragma unroll
        for (int t = 0; t < 16; t++) facc[t] = 0.0f;
        for (int m4 = 0; m4 < 32; m4++) {
            int m = m4 * 4;
            float w0 = wo[(m + 0) * 128 + o], w1 = wo[(m + 1) * 128 + o];
            float w2 = wo[(m + 2) * 128 + o], w3 = wo[(m + 3) * 128 + o];
#pragma unroll
            for (int t = 0; t < 16; t++) {
                float4 v = ((const float4*)tmp_s)[t * 32 + m4];
                facc[t] += v.x * w0 + v.y * w1 + v.z * w2 + v.w * w3;
            }
        }
        float bv = bo[o];
#pragma unroll
        for (int t = 0; t < 16; t++) g_z[(tok0 + t) * 128 + o] += facc[t] + bv;
    }
}

// ---------------- final LN + head ----------------
__global__ void __launch_bounds__(256) k_final(
    const float* __restrict__ g, const float* __restrict__ b,
    const float* __restrict__ ow, const float* __restrict__ ob,
    float* __restrict__ out)
{
    int warp = threadIdx.x >> 5, lane = threadIdx.x & 31;
    int n = blockIdx.x * 8 + warp;
    float4 v = ((const float4*)g_z)[n * 32 + lane];
    float s = warp_sum(v.x + v.y + v.z + v.w);
    float mu = s * (1.0f / 128.0f);
    float q = warp_sum(v.x * v.x + v.y * v.y + v.z * v.z + v.w * v.w);
    float var = q * (1.0f / 128.0f) - mu * mu;
    float inv = rsqrtf(var + 1e-5f);
    float4 gg = ((const float4*)g)[lane];
    float4 bb = ((const float4*)b)[lane];
    float4 w4 = ((const float4*)ow)[lane];
    float y0 = (v.x - mu) * inv * gg.x + bb.x;
    float y1 = (v.y - mu) * inv * gg.y + bb.y;
    float y2 = (v.z - mu) * inv * gg.z + bb.z;
    float y3 = (v.w - mu) * inv * gg.w + bb.w;
    float p = warp_sum(y0 * w4.x + y1 * w4.y + y2 * w4.z + y3 * w4.w);
    if (lane == 0) out[n] = p + ob[0];
}

// ---------------- host launch ----------------
extern "C" void kernel_launch(void* const* d_in, const int* in_sizes, int n_in,
                              void* d_out, int out_size)
{
    const float* x        = (const float*)d_in[0];
    const float* fx       = (const float*)d_in[1];
    const float* pre_w1   = (const float*)d_in[2];
    const float* pre_b1   = (const float*)d_in[3];
    const float* pre_w2   = (const float*)d_in[4];
    const float* pre_b2   = (const float*)d_in[5];
    const float* place    = (const float*)d_in[6];
    const float* ln1_g    = (const float*)d_in[7];
    const float* ln1_b    = (const float*)d_in[8];
    const float* convx_w  = (const float*)d_in[9];
    const float* convx_b  = (const float*)d_in[10];
    const float* convfx_w = (const float*)d_in[11];
    const float* convfx_b = (const float*)d_in[12];
    const float* slice_w  = (const float*)d_in[13];
    const float* slice_b  = (const float*)d_in[14];
    const float* temp     = (const float*)d_in[15];
    const float* wq       = (const float*)d_in[16];
    const float* wk       = (const float*)d_in[17];
    const float* wv       = (const float*)d_in[18];
    const float* wo       = (const float*)d_in[19];
    const float* bo       = (const float*)d_in[20];
    const float* ln2_g    = (const float*)d_in[21];
    const float* ln2_b    = (const float*)d_in[22];
    const float* mlp_w1   = (const float*)d_in[23];
    const float* mlp_b1   = (const float*)d_in[24];
    const float* mlp_w2   = (const float*)d_in[25];
    const float* mlp_b2   = (const float*)d_in[26];
    const float* ln3_g    = (const float*)d_in[27];
    const float* ln3_b    = (const float*)d_in[28];
    const float* out_w    = (const float*)d_in[29];
    const float* out_b    = (const float*)d_in[30];
    float* out = (float*)d_out;

    cudaFuncSetAttribute(k_conv_mma,
                         cudaFuncAttributeMaxDynamicSharedMemorySize, CONV_SMEM);
    cudaFuncSetAttribute(k_mlp_mma,
                         cudaFuncAttributeMaxDynamicSharedMemorySize, MLP_SMEM);

    k_cvt_frag<<<864, 256>>>(convx_w, convfx_w);
    k_cvt_mlp<<<32, 256>>>(mlp_w1, mlp_w2);
    k_pre<<<NTOK / 32, 128>>>(x, fx, pre_w1, pre_b1, pre_w2, pre_b2, place);

    for (int l = 0; l < 2; l++) {
        k_ln<<<NTOK / 8, 256>>>(ln1_g + l * 128, ln1_b + l * 128, 1);
        k_conv_mma<<<dim3(8, 32, 2), 256, CONV_SMEM>>>(
            convx_b + l * 128, convfx_b + l * 128, l);
        k_slice<<<128, 256>>>(slice_w + l * 512, slice_b + l * 32, temp + l * 8);
        k_attn<<<1, 256>>>(wq + l * 256, wk + l * 256, wv + l * 256);
        k_deslice<<<NTOK / 16, 128>>>(wo + l * 16384, bo + l * 128);
        k_ln<<<NTOK / 8, 256>>>(ln2_g + l * 128, ln2_b + l * 128, 0);
        k_mlp_mma<<<NTOK / 128, 256, MLP_SMEM>>>(
            mlp_b1 + l * 128, mlp_b2 + l * 128, l);
    }
    k_final<<<NTOK / 8, 256>>>(ln3_g, ln3_b, out_w, out_b, out);
}

// round 17
// speedup vs baseline: 5.0005x; 1.0977x over previous
#include <cuda_runtime.h>
#include <cuda_fp16.h>
#include <math.h>
#include <stdint.h>

#define NTOK 32768
#define C 128
#define XP 40   // fp16 pitch for ic dimension (conflict-free ldmatrix)

// ---------------- device scratch (no allocations allowed) ----------------
__device__ float g_z[NTOK * C];      // residual stream
__device__ float g_xmid[NTOK * C];   // conv-x output
__device__ float g_fxmid[NTOK * C];  // conv-fx output
__device__ float g_swt[NTOK * 256];  // slice weights [n][h][g]
__device__ float g_norm[256];        // [h][g]
__device__ float g_toknum[4096];     // [h][g][dh]
__device__ float g_ot[4096];         // [h][g][dh]
__device__ __half g_znh[NTOK * C];   // LN output (fp16, mma A operand)
// conv weights in mma B-fragment order (fp16 hi/lo split):
// [sel][tap][kc(8)][npg(8)][lane(32)] -> uint4 = regs (m0,m1,m2,m3)
__device__ uint4 g_wfh[4 * 27 * 8 * 8 * 32];
__device__ uint4 g_wfl[4 * 27 * 8 * 8 * 32];
// mlp weights in mma B-fragment order: [layer][mat][kc(8)][npg(8)][lane(32)]
__device__ uint4 g_mwh[2 * 2 * 8 * 8 * 32];
__device__ uint4 g_mwl[2 * 2 * 8 * 8 * 32];

__device__ __forceinline__ float gelu_exact(float v) {
    return 0.5f * v * (1.0f + erff(v * 0.70710678118654752f));
}

__device__ __forceinline__ float warp_sum(float s) {
#pragma unroll
    for (int o = 16; o; o >>= 1) s += __shfl_xor_sync(0xffffffffu, s, o);
    return s;
}
__device__ __forceinline__ float warp_max(float s) {
#pragma unroll
    for (int o = 16; o; o >>= 1) s = fmaxf(s, __shfl_xor_sync(0xffffffffu, s, o));
    return s;
}

__device__ __forceinline__ void ldsm4(uint32_t* r, uint32_t addr) {
    asm volatile("ldmatrix.sync.aligned.m8n8.x4.shared.b16 {%0,%1,%2,%3}, [%4];"
        : "=r"(r[0]), "=r"(r[1]), "=r"(r[2]), "=r"(r[3]) : "r"(addr));
}
__device__ __forceinline__ void mma_f16(float* d, const uint32_t* a,
                                        uint32_t b0, uint32_t b1) {
    asm volatile(
        "mma.sync.aligned.m16n8k16.row.col.f32.f16.f16.f32 "
        "{%0,%1,%2,%3}, {%4,%5,%6,%7}, {%8,%9}, {%0,%1,%2,%3};"
        : "+f"(d[0]), "+f"(d[1]), "+f"(d[2]), "+f"(d[3])
        : "r"(a[0]), "r"(a[1]), "r"(a[2]), "r"(a[3]), "r"(b0), "r"(b1));
}

__device__ __forceinline__ void split_pack(float v0, float v1,
                                           uint32_t& hh, uint32_t& ll) {
    __half h0 = __float2half_rn(v0), h1 = __float2half_rn(v1);
    float r0 = v0 - __half2float(h0), r1 = v1 - __half2float(h1);
    __half l0 = __float2half_rn(r0), l1 = __float2half_rn(r1);
    hh = (uint32_t)__half_as_ushort(h0) | ((uint32_t)__half_as_ushort(h1) << 16);
    ll = (uint32_t)__half_as_ushort(l0) | ((uint32_t)__half_as_ushort(l1) << 16);
}

// ---------------- conv weight conversion: fp32 [oc][ic][tap] -> B-fragment uint4 ----
__global__ void __launch_bounds__(256) k_cvt_frag(
    const float* __restrict__ wx, const float* __restrict__ wf)
{
    int idx = blockIdx.x * 256 + threadIdx.x;   // < 221184
    int lane = idx & 31;
    int npg = (idx >> 5) & 7;
    int kc = (idx >> 8) & 7;
    int rest = idx >> 11;       // sel*27 + tap, 0..107
    int tap = rest % 27;
    int sel = rest / 27;
    const float* src = ((sel & 1) ? wf : wx) + (sel >> 1) * 442368;
    int oc0 = npg * 16 + (lane >> 2);
    int k0 = kc * 16 + 2 * (lane & 3);
    uint32_t h[4], l[4];
#pragma unroll
    for (int m = 0; m < 4; m++) {
        int oc = oc0 + ((m >> 1) << 3);
        int kk = k0 + ((m & 1) << 3);
        split_pack(src[(oc * 128 + kk) * 27 + tap],
                   src[(oc * 128 + kk + 1) * 27 + tap], h[m], l[m]);
    }
    g_wfh[idx] = make_uint4(h[0], h[1], h[2], h[3]);
    g_wfl[idx] = make_uint4(l[0], l[1], l[2], l[3]);
}

// ---------------- mlp weight conversion: fp32 [c_in][c_out] -> B-fragment uint4 -----
__global__ void __launch_bounds__(256) k_cvt_mlp(
    const float* __restrict__ w1, const float* __restrict__ w2)
{
    int idx = blockIdx.x * 256 + threadIdx.x;   // < 8192
    int lane = idx & 31;
    int npg = (idx >> 5) & 7;
    int kc = (idx >> 8) & 7;
    int rest = idx >> 11;       // layer*2 + mat
    const float* src = ((rest & 1) ? w2 : w1) + (rest >> 1) * 16384;
    int oc0 = npg * 16 + (lane >> 2);
    int k0 = kc * 16 + 2 * (lane & 3);
    uint32_t h[4], l[4];
#pragma unroll
    for (int m = 0; m < 4; m++) {
        int oc = oc0 + ((m >> 1) << 3);
        int kk = k0 + ((m & 1) << 3);
        split_pack(src[kk * 128 + oc], src[(kk + 1) * 128 + oc], h[m], l[m]);
    }
    g_mwh[idx] = make_uint4(h[0], h[1], h[2], h[3]);
    g_mwl[idx] = make_uint4(l[0], l[1], l[2], l[3]);
}

// ---------------- pre-MLP: z = gelu(h@W1+b1)@W2+b2+placeholder ----------------
__global__ void __launch_bounds__(128) k_pre(
    const float* __restrict__ x, const float* __restrict__ fx,
    const float* __restrict__ W1, const float* __restrict__ b1,
    const float* __restrict__ W2, const float* __restrict__ b2,
    const float* __restrict__ ph)
{
    __shared__ float h_s[32 * 4];
    __shared__ float mid_s[32 * 256];
    int tid = threadIdx.x;
    int tok0 = blockIdx.x * 32;

    for (int i = tid; i < 128; i += 128) {
        int t = i >> 2, j = i & 3;
        h_s[i] = (j < 3) ? x[(tok0 + t) * 3 + j] : fx[tok0 + t];
    }
    __syncthreads();

#pragma unroll
    for (int rep = 0; rep < 2; rep++) {
        int m = tid + rep * 128;
        float w0 = W1[0 * 256 + m], w1 = W1[1 * 256 + m];
        float w2 = W1[2 * 256 + m], w3 = W1[3 * 256 + m];
        float bb = b1[m];
#pragma unroll
        for (int t = 0; t < 32; t++) {
            float4 hv = ((const float4*)h_s)[t];
            float v = bb + hv.x * w0 + hv.y * w1 + hv.z * w2 + hv.w * w3;
            mid_s[t * 256 + m] = gelu_exact(v);
        }
    }
    __syncthreads();

    int o = tid;
    float acc[32];
#pragma unroll
    for (int t = 0; t < 32; t++) acc[t] = 0.0f;
    for (int m4 = 0; m4 < 64; m4++) {
        int m = m4 * 4;
        float w0 = W2[(m + 0) * 128 + o], w1 = W2[(m + 1) * 128 + o];
        float w2 = W2[(m + 2) * 128 + o], w3 = W2[(m + 3) * 128 + o];
#pragma unroll
        for (int t = 0; t < 32; t++) {
            float4 v = ((const float4*)mid_s)[t * 64 + m4];
            acc[t] += v.x * w0 + v.y * w1 + v.z * w2 + v.w * w3;
        }
    }
    float bb = b2[o] + ph[o];
#pragma unroll
    for (int t = 0; t < 32; t++) g_z[(tok0 + t) * 128 + o] = acc[t] + bb;
}

// ---------------- LayerNorm: znh = fp16(LN(z)*g+b); optional acc zeroing ----------
__global__ void __launch_bounds__(256) k_ln(
    const float* __restrict__ g, const float* __restrict__ b, int dozero)
{
    if (dozero && blockIdx.x == 0) {
        int t = threadIdx.x;
        g_norm[t] = 0.0f;
        for (int i = t; i < 4096; i += 256) g_toknum[i] = 0.0f;
    }
    int warp = threadIdx.x >> 5, lane = threadIdx.x & 31;
    int n = blockIdx.x * 8 + warp;
    float4 v = ((const float4*)g_z)[n * 32 + lane];
    float s = warp_sum(v.x + v.y + v.z + v.w);
    float mu = s * (1.0f / 128.0f);
    float q = warp_sum(v.x * v.x + v.y * v.y + v.z * v.z + v.w * v.w);
    float var = q * (1.0f / 128.0f) - mu * mu;
    float inv = rsqrtf(var + 1e-5f);
    float4 gg = ((const float4*)g)[lane];
    float4 bb = ((const float4*)b)[lane];
    float y0 = (v.x - mu) * inv * gg.x + bb.x;
    float y1 = (v.y - mu) * inv * gg.y + bb.y;
    float y2 = (v.z - mu) * inv * gg.z + bb.z;
    float y3 = (v.w - mu) * inv * gg.w + bb.w;
    __half2 p0 = __floats2half2_rn(y0, y1);
    __half2 p1 = __floats2half2_rn(y2, y3);
    ((__half2*)g_znh)[n * 64 + lane * 2 + 0] = p0;
    ((__half2*)g_znh)[n * 64 + lane * 2 + 1] = p1;
}

// ---------------- conv3d 3x3x3 via fp16 tensor cores (fragment-LDG B) --------------
// grid (8 j-tiles, 32 i, 2 conv). Block 256 thr = 8 warps, 2 CTAs/SM.
// Block tile: 128 tokens x 128 oc. Warp tile: 64 tokens (2 j-lines) x 32 oc
// -> B fragment LDG per (t,ks) drops 16 -> 4 (hi+lo), A ldsm 2 -> 4.
#define CONV_SMEM (612 * XP * 2 + 512)
__global__ void __launch_bounds__(256, 2) k_conv_mma(
    const float* __restrict__ bx, const float* __restrict__ bf, int layer)
{
    extern __shared__ char sm_raw[];
    float* bias_s = (float*)(sm_raw + 612 * XP * 2);

    const int tid = threadIdx.x, lane = tid & 31, warp = tid >> 5;
    const int z = blockIdx.z;
    const int sel = layer * 2 + z;
    const float* bias = z ? bf : bx;
    float* out = z ? g_fxmid : g_xmid;
    const int jp = warp >> 2;   // token half: j-lines {jp*2, jp*2+1}
    const int og = warp & 3;    // oc quarter: og*32

    uint32_t su = (uint32_t)__cvta_generic_to_shared(sm_raw);
    const uint32_t xs_u = su;

    if (tid < 128) bias_s[tid] = bias[tid];

    const uint4* __restrict__ wfh = g_wfh + sel * 55296;
    const uint4* __restrict__ wfl = g_wfl + sel * 55296;

    float acc[16][4];   // [mg*4 + np*2 + h]
#pragma unroll
    for (int n = 0; n < 16; n++) {
        acc[n][0] = acc[n][1] = acc[n][2] = acc[n][3] = 0.f;
    }

    const int r15 = lane & 15;
    const int csel = (lane >> 4) * 16;

    for (int cb = 0; cb < 4; cb++) {
        __syncthreads();
        // stage halo neighborhood (3x6x34 positions x 32 ic) fp16
        for (int idx = tid; idx < 2448; idx += 256) {
            int pos = idx >> 2, q = idx & 3;
            int ii = pos / 204; int rem = pos - ii * 204;
            int jj = rem / 34;  int kk = rem - jj * 34;
            int gi = (int)blockIdx.y + ii - 1;
            int gj = (int)blockIdx.x * 4 + jj - 1;
            int gk = kk - 1;
            uint4 v = make_uint4(0u, 0u, 0u, 0u);
            if ((unsigned)gi < 32u && (unsigned)gj < 32u && (unsigned)gk < 32u) {
                int tokn = (gi << 10) + (gj << 5) + gk;
                v = ((const uint4*)g_znh)[tokn * 16 + cb * 4 + q];
            }
            char* dst = sm_raw + pos * (XP * 2) + q * 16;
            *(uint4*)dst = v;
        }
        __syncthreads();

#pragma unroll 1
        for (int t = 0; t < 27; t++) {
            int a = t / 9; int rem9 = t - a * 9;
            int bj = rem9 / 3; int cc = rem9 - bj * 3;
#pragma unroll
            for (int ks = 0; ks < 2; ks++) {
                int kci = cb * 2 + ks;
                uint32_t A[4][4];
#pragma unroll
                for (int mg = 0; mg < 4; mg++) {
                    int jl = jp * 2 + (mg >> 1);
                    int koff = (mg & 1) * 16;
                    uint32_t off = (uint32_t)((((a * 6 + jl + bj) * 34)
                                   + koff + r15 + cc) * (XP * 2)) + csel + ks * 32;
                    ldsm4(A[mg], xs_u + off);
                }
                const uint4* bh = wfh + ((t * 8 + kci) * 8 + og * 2) * 32 + lane;
                const uint4* bl = wfl + ((t * 8 + kci) * 8 + og * 2) * 32 + lane;
#pragma unroll
                for (int np = 0; np < 2; np++) {
                    uint4 Bh = bh[np * 32];
                    uint4 Bl = bl[np * 32];
#pragma unroll
                    for (int mg = 0; mg < 4; mg++) {
                        mma_f16(acc[mg * 4 + np * 2 + 0], A[mg], Bh.x, Bh.y);
                        mma_f16(acc[mg * 4 + np * 2 + 0], A[mg], Bl.x, Bl.y);
                        mma_f16(acc[mg * 4 + np * 2 + 1], A[mg], Bh.z, Bh.w);
                        mma_f16(acc[mg * 4 + np * 2 + 1], A[mg], Bl.z, Bl.w);
                    }
                }
            }
        }
    }

    // epilogue: acc + bias -> out (fp32)
    int gi = blockIdx.y;
#pragma unroll
    for (int mg = 0; mg < 4; mg++) {
        int jl = jp * 2 + (mg >> 1);
        int gj = blockIdx.x * 4 + jl;
        int tk = (gi << 10) + (gj << 5) + (mg & 1) * 16 + (lane >> 2);
#pragma unroll
        for (int np = 0; np < 2; np++) {
#pragma unroll
            for (int h = 0; h < 2; h++) {
                float* a = acc[mg * 4 + np * 2 + h];
                int col = og * 32 + np * 16 + h * 8 + (lane & 3) * 2;
                float b0 = bias_s[col], b1 = bias_s[col + 1];
                *(float2*)&out[tk * 128 + col] = make_float2(a[0] + b0, a[1] + b1);
                *(float2*)&out[(tk + 8) * 128 + col] = make_float2(a[2] + b0, a[3] + b1);
            }
        }
    }
}

// ---------------- MLP via fp16 tensor cores: z += gelu(znh@W1+b1)@W2+b2 ------------
#define MLP_PITCH 272   // bytes per row (136 fp16 = 17 x 16B, odd -> conflict-free)
#define MLP_SMEM (2 * 128 * MLP_PITCH + 1024)
__global__ void __launch_bounds__(256, 2) k_mlp_mma(
    const float* __restrict__ b1, const float* __restrict__ b2, int layer)
{
    extern __shared__ char sm_raw[];
    float* bias_s = (float*)(sm_raw + 2 * 128 * MLP_PITCH);
    const int tid = threadIdx.x, lane = tid & 31, warp = tid >> 5;
    const int tg = warp >> 1, og = warp & 1;
    const int tok0 = blockIdx.x * 128;
    uint32_t su = (uint32_t)__cvta_generic_to_shared(sm_raw);
    const uint32_t a_u = su;
    const uint32_t mid_u = su + 128 * MLP_PITCH;

    bias_s[tid] = (tid < 128) ? b1[tid] : b2[tid - 128];

    for (int idx = tid; idx < 2048; idx += 256) {
        int row = idx >> 4, q = idx & 15;
        uint4 v = ((const uint4*)g_znh)[(tok0 + row) * 16 + q];
        *(uint4*)(sm_raw + row * MLP_PITCH + q * 16) = v;
    }
    __syncthreads();

    const int r15 = lane & 15, csel = (lane >> 4) * 16;
    const uint4* wh1 = g_mwh + (layer * 2 + 0) * 2048;
    const uint4* wl1 = g_mwl + (layer * 2 + 0) * 2048;
    const uint4* wh2 = g_mwh + (layer * 2 + 1) * 2048;
    const uint4* wl2 = g_mwl + (layer * 2 + 1) * 2048;

    float acc[16][4];
#pragma unroll
    for (int n = 0; n < 16; n++)
        acc[n][0] = acc[n][1] = acc[n][2] = acc[n][3] = 0.f;

#pragma unroll 1
    for (int kc = 0; kc < 8; kc++) {
        uint32_t off0 = (uint32_t)((tg * 32 + r15) * MLP_PITCH) + kc * 32 + csel;
        uint32_t off1 = off0 + 16 * MLP_PITCH;
        uint32_t Ah0[4], Ah1[4];
        ldsm4(Ah0, a_u + off0);
        ldsm4(Ah1, a_u + off1);
        const uint4* bh = wh1 + kc * 256 + og * 128 + lane;
        const uint4* bl = wl1 + kc * 256 + og * 128 + lane;
#pragma unroll
        for (int np = 0; np < 4; np++) {
            uint4 Bh = bh[np * 32];
            uint4 Bl = bl[np * 32];
            mma_f16(acc[np * 2 + 0], Ah0, Bh.x, Bh.y);
            mma_f16(acc[np * 2 + 0], Ah0, Bl.x, Bl.y);
            mma_f16(acc[np * 2 + 1], Ah0, Bh.z, Bh.w);
            mma_f16(acc[np * 2 + 1], Ah0, Bl.z, Bl.w);
            mma_f16(acc[8 + np * 2 + 0], Ah1, Bh.x, Bh.y);
            mma_f16(acc[8 + np * 2 + 0], Ah1, Bl.x, Bl.y);
            mma_f16(acc[8 + np * 2 + 1], Ah1, Bh.z, Bh.w);
            mma_f16(acc[8 + np * 2 + 1], Ah1, Bl.z, Bl.w);
        }
    }

#pragma unroll
    for (int mg = 0; mg < 2; mg++) {
#pragma unroll
        for (int np = 0; np < 4; np++) {
#pragma unroll
            for (int h = 0; h < 2; h++) {
                float* a = acc[mg * 8 + np * 2 + h];
                int col = og * 64 + np * 16 + h * 8 + (lane & 3) * 2;
                int row = tg * 32 + mg * 16 + (lane >> 2);
                float bb0 = bias_s[col], bb1 = bias_s[col + 1];
                __half2 v0 = __floats2half2_rn(gelu_exact(a[0] + bb0),
                                               gelu_exact(a[1] + bb1));
                __half2 v1 = __floats2half2_rn(gelu_exact(a[2] + bb0),
                                               gelu_exact(a[3] + bb1));
                *(__half2*)(sm_raw + 128 * MLP_PITCH + row * MLP_PITCH + col * 2) = v0;
                *(__half2*)(sm_raw + 128 * MLP_PITCH + (row + 8) * MLP_PITCH + col * 2) = v1;
            }
        }
    }
    __syncthreads();

#pragma unroll
    for (int n = 0; n < 16; n++)
        acc[n][0] = acc[n][1] = acc[n][2] = acc[n][3] = 0.f;

#pragma unroll 1
    for (int kc = 0; kc < 8; kc++) {
        uint32_t off0 = (uint32_t)((tg * 32 + r15) * MLP_PITCH) + kc * 32 + csel;
        uint32_t off1 = off0 + 16 * MLP_PITCH;
        uint32_t Ah0[4], Ah1[4];
        ldsm4(Ah0, mid_u + off0);
        ldsm4(Ah1, mid_u + off1);
        const uint4* bh = wh2 + kc * 256 + og * 128 + lane;
        const uint4* bl = wl2 + kc * 256 + og * 128 + lane;
#pragma unroll
        for (int np = 0; np < 4; np++) {
            uint4 Bh = bh[np * 32];
            uint4 Bl = bl[np * 32];
            mma_f16(acc[np * 2 + 0], Ah0, Bh.x, Bh.y);
            mma_f16(acc[np * 2 + 0], Ah0, Bl.x, Bl.y);
            mma_f16(acc[np * 2 + 1], Ah0, Bh.z, Bh.w);
            mma_f16(acc[np * 2 + 1], Ah0, Bl.z, Bl.w);
            mma_f16(acc[8 + np * 2 + 0], Ah1, Bh.x, Bh.y);
            mma_f16(acc[8 + np * 2 + 0], Ah1, Bl.x, Bl.y);
            mma_f16(acc[8 + np * 2 + 1], Ah1, Bh.z, Bh.w);
            mma_f16(acc[8 + np * 2 + 1], Ah1, Bl.z, Bl.w);
        }
    }

#pragma unroll
    for (int mg = 0; mg < 2; mg++) {
#pragma unroll
        for (int np = 0; np < 4; np++) {
#pragma unroll
            for (int h = 0; h < 2; h++) {
                float* a = acc[mg * 8 + np * 2 + h];
                int col = og * 64 + np * 16 + h * 8 + (lane & 3) * 2;
                int row = tg * 32 + mg * 16 + (lane >> 2);
                float bb0 = bias_s[128 + col], bb1 = bias_s[128 + col + 1];
                float2 r0 = *(float2*)&g_z[(tok0 + row) * 128 + col];
                float2 r1 = *(float2*)&g_z[(tok0 + row + 8) * 128 + col];
                *(float2*)&g_z[(tok0 + row) * 128 + col] =
                    make_float2(a[0] + bb0 + r0.x, a[1] + bb1 + r0.y);
                *(float2*)&g_z[(tok0 + row + 8) * 128 + col] =
                    make_float2(a[2] + bb0 + r1.x, a[3] + bb1 + r1.y);
            }
        }
    }
}

// ---------------- slice softmax + N-reductions (64-token staging rounds) ----------
#define SLICE_SMEM ((2 * 8192 + 512 + 32) * 4)
__global__ void __launch_bounds__(256) k_slice(
    const float* __restrict__ sw, const float* __restrict__ sb,
    const float* __restrict__ temp)
{
    extern __shared__ float sl_s[];
    float* xm_s = sl_s;              // 8192
    float* fx_s = sl_s + 8192;       // 8192
    float* sw_s = sl_s + 16384;      // 512
    float* sb_s = sw_s + 512;        // 32
    int tid = threadIdx.x;
    int h = tid >> 5;
    int g = tid & 31;
    for (int i = tid; i < 512; i += 256) sw_s[i] = sw[i];
    if (tid < 32) sb_s[tid] = sb[tid];
    float invt = 1.0f / temp[h];
    float nacc = 0.0f;
    float tacc[16];
#pragma unroll
    for (int d = 0; d < 16; d++) tacc[d] = 0.0f;
    int tok0 = blockIdx.x * 256;

    for (int rnd = 0; rnd < 4; rnd++) {
        __syncthreads();
        int tb = tok0 + rnd * 64;
        for (int i = tid; i < 8192; i += 256) {
            xm_s[i] = g_xmid[tb * 128 + i];
            fx_s[i] = g_fxmid[tb * 128 + i];
        }
        __syncthreads();
#pragma unroll 1
        for (int t = 0; t < 64; t++) {
            float lg = sb_s[g];
#pragma unroll
            for (int d = 0; d < 16; d++) lg += xm_s[t * 128 + h * 16 + d] * sw_s[d * 32 + g];
            lg *= invt;
            float m = warp_max(lg);
            float e = expf(lg - m);
            float s = warp_sum(e);
            float w = e / s;
            g_swt[(tb + t) * 256 + tid] = w;
            nacc += w;
#pragma unroll
            for (int d = 0; d < 16; d++) tacc[d] += fx_s[t * 128 + h * 16 + d] * w;
        }
    }
    atomicAdd(&g_norm[tid], nacc);
#pragma unroll
    for (int d = 0; d < 16; d++) atomicAdd(&g_toknum[tid * 16 + d], tacc[d]);
}

// ---------------- tiny slice attention (1 block, 256 threads) ----------------
__global__ void __launch_bounds__(256) k_attn(
    const float* __restrict__ wq, const float* __restrict__ wk,
    const float* __restrict__ wv)
{
    __shared__ float k_s[4096];
    __shared__ float v_s[4096];
    int tid = threadIdx.x;
    int h = tid >> 5;
    float tokr[16];
    float nrm = g_norm[tid] + 1e-5f;
#pragma unroll
    for (int d = 0; d < 16; d++) tokr[d] = g_toknum[tid * 16 + d] / nrm;
    float q[16];
#pragma unroll
    for (int dd = 0; dd < 16; dd++) {
        float aq = 0.f, ak = 0.f, av = 0.f;
#pragma unroll
        for (int d = 0; d < 16; d++) {
            aq += tokr[d] * wq[d * 16 + dd];
            ak += tokr[d] * wk[d * 16 + dd];
            av += tokr[d] * wv[d * 16 + dd];
        }
        q[dd] = aq;
        k_s[tid * 16 + dd] = ak;
        v_s[tid * 16 + dd] = av;
    }
    __syncthreads();
    float p[32];
    float mx = -1e30f;
#pragma unroll 1
    for (int g2 = 0; g2 < 32; g2++) {
        float s = 0.f;
#pragma unroll
        for (int d = 0; d < 16; d++) s += q[d] * k_s[(h * 32 + g2) * 16 + d];
        s *= 0.25f;
        p[g2] = s;
        mx = fmaxf(mx, s);
    }
    float sum = 0.f;
#pragma unroll
    for (int g2 = 0; g2 < 32; g2++) { p[g2] = expf(p[g2] - mx); sum += p[g2]; }
    float inv = 1.0f / sum;
#pragma unroll 1
    for (int c = 0; c < 16; c++) {
        float o = 0.f;
#pragma unroll
        for (int g2 = 0; g2 < 32; g2++) o += p[g2] * v_s[(h * 32 + g2) * 16 + c];
        g_ot[tid * 16 + c] = o * inv;
    }
}

// ---------------- de-slice + wo projection + residual ----------------
__global__ void __launch_bounds__(128) k_deslice(
    const float* __restrict__ wo, const float* __restrict__ bo)
{
    __shared__ float swt_s[16 * 256];
    __shared__ float tmp_s[16 * 128];
    int tid = threadIdx.x;
    int tok0 = blockIdx.x * 16;
    for (int i = tid; i < 4096; i += 128) swt_s[i] = g_swt[tok0 * 256 + i];
    __syncthreads();
    {
        int c = tid, h = c >> 4, cc = c & 15;
        float acc[16];
#pragma unroll
        for (int t = 0; t < 16; t++) acc[t] = 0.0f;
        for (int g = 0; g < 32; g++) {
            float ov = g_ot[(h * 32 + g) * 16 + cc];
#pragma unroll
            for (int t = 0; t < 16; t++) acc[t] += swt_s[t * 256 + h * 32 + g] * ov;
        }
#pragma unroll
        for (int t = 0; t < 16; t++) tmp_s[t * 128 + c] = acc[t];
    }
    __syncthreads();
    {
        int o = tid;
        float facc[16];
#pragma unroll
        for (int t = 0; t < 16; t++) facc[t] = 0.0f;
        for (int m4 = 0; m4 < 32; m4++) {
            int m = m4 * 4;
            float w0 = wo[(m + 0) * 128 + o], w1 = wo[(m + 1) * 128 + o];
            float w2 = wo[(m + 2) * 128 + o], w3 = wo[(m + 3) * 128 + o];
#pragma unroll
            for (int t = 0; t < 16; t++) {
                float4 v = ((const float4*)tmp_s)[t * 32 + m4];
                facc[t] += v.x * w0 + v.y * w1 + v.z * w2 + v.w * w3;
            }
        }
        float bv = bo[o];
#pragma unroll
        for (int t = 0; t < 16; t++) g_z[(tok0 + t) * 128 + o] += facc[t] + bv;
    }
}

// ---------------- final LN + head ----------------
__global__ void __launch_bounds__(256) k_final(
    const float* __restrict__ g, const float* __restrict__ b,
    const float* __restrict__ ow, const float* __restrict__ ob,
    float* __restrict__ out)
{
    int warp = threadIdx.x >> 5, lane = threadIdx.x & 31;
    int n = blockIdx.x * 8 + warp;
    float4 v = ((const float4*)g_z)[n * 32 + lane];
    float s = warp_sum(v.x + v.y + v.z + v.w);
    float mu = s * (1.0f / 128.0f);
    float q = warp_sum(v.x * v.x + v.y * v.y + v.z * v.z + v.w * v.w);
    float var = q * (1.0f / 128.0f) - mu * mu;
    float inv = rsqrtf(var + 1e-5f);
    float4 gg = ((const float4*)g)[lane];
    float4 bb = ((const float4*)b)[lane];
    float4 w4 = ((const float4*)ow)[lane];
    float y0 = (v.x - mu) * inv * gg.x + bb.x;
    float y1 = (v.y - mu) * inv * gg.y + bb.y;
    float y2 = (v.z - mu) * inv * gg.z + bb.z;
    float y3 = (v.w - mu) * inv * gg.w + bb.w;
    float p = warp_sum(y0 * w4.x + y1 * w4.y + y2 * w4.z + y3 * w4.w);
    if (lane == 0) out[n] = p + ob[0];
}

// ---------------- host launch ----------------
extern "C" void kernel_launch(void* const* d_in, const int* in_sizes, int n_in,
                              void* d_out, int out_size)
{
    const float* x        = (const float*)d_in[0];
    const float* fx       = (const float*)d_in[1];
    const float* pre_w1   = (const float*)d_in[2];
    const float* pre_b1   = (const float*)d_in[3];
    const float* pre_w2   = (const float*)d_in[4];
    const float* pre_b2   = (const float*)d_in[5];
    const float* place    = (const float*)d_in[6];
    const float* ln1_g    = (const float*)d_in[7];
    const float* ln1_b    = (const float*)d_in[8];
    const float* convx_w  = (const float*)d_in[9];
    const float* convx_b  = (const float*)d_in[10];
    const float* convfx_w = (const float*)d_in[11];
    const float* convfx_b = (const float*)d_in[12];
    const float* slice_w  = (const float*)d_in[13];
    const float* slice_b  = (const float*)d_in[14];
    const float* temp     = (const float*)d_in[15];
    const float* wq       = (const float*)d_in[16];
    const float* wk       = (const float*)d_in[17];
    const float* wv       = (const float*)d_in[18];
    const float* wo       = (const float*)d_in[19];
    const float* bo       = (const float*)d_in[20];
    const float* ln2_g    = (const float*)d_in[21];
    const float* ln2_b    = (const float*)d_in[22];
    const float* mlp_w1   = (const float*)d_in[23];
    const float* mlp_b1   = (const float*)d_in[24];
    const float* mlp_w2   = (const float*)d_in[25];
    const float* mlp_b2   = (const float*)d_in[26];
    const float* ln3_g    = (const float*)d_in[27];
    const float* ln3_b    = (const float*)d_in[28];
    const float* out_w    = (const float*)d_in[29];
    const float* out_b    = (const float*)d_in[30];
    float* out = (float*)d_out;

    cudaFuncSetAttribute(k_conv_mma,
                         cudaFuncAttributeMaxDynamicSharedMemorySize, CONV_SMEM);
    cudaFuncSetAttribute(k_mlp_mma,
                         cudaFuncAttributeMaxDynamicSharedMemorySize, MLP_SMEM);
    cudaFuncSetAttribute(k_slice,
                         cudaFuncAttributeMaxDynamicSharedMemorySize, SLICE_SMEM);

    k_cvt_frag<<<864, 256>>>(convx_w, convfx_w);
    k_cvt_mlp<<<32, 256>>>(mlp_w1, mlp_w2);
    k_pre<<<NTOK / 32, 128>>>(x, fx, pre_w1, pre_b1, pre_w2, pre_b2, place);

    for (int l = 0; l < 2; l++) {
        k_ln<<<NTOK / 8, 256>>>(ln1_g + l * 128, ln1_b + l * 128, 1);
        k_conv_mma<<<dim3(8, 32, 2), 256, CONV_SMEM>>>(
            convx_b + l * 128, convfx_b + l * 128, l);
        k_slice<<<128, 256, SLICE_SMEM>>>(slice_w + l * 512, slice_b + l * 32,
                                          temp + l * 8);
        k_attn<<<1, 256>>>(wq + l * 256, wk + l * 256, wv + l * 256);
        k_deslice<<<NTOK / 16, 128>>>(wo + l * 16384, bo + l * 128);
        k_ln<<<NTOK / 8, 256>>>(ln2_g + l * 128, ln2_b + l * 128, 0);
        k_mlp_mma<<<NTOK / 128, 256, MLP_SMEM>>>(
            mlp_b1 + l * 128, mlp_b2 + l * 128, l);
    }
    k_final<<<NTOK / 8, 256>>>(ln3_g, ln3_b, out_w, out_b, out);
}